// round 3
// baseline (speedup 1.0000x reference)
#include <cuda_runtime.h>
#include <cstdint>

#define N_   1024
#define S_   144
#define R_   96
#define K_   128
#define D_   768
#define ABL_ 48
#define RK_  (R_ * K_)   // 12288

// Scratch: device globals (no allocation allowed in kernel_launch)
__device__ float g_coeffs[(size_t)N_ * RK_];  // 50.3 MB
__device__ float g_lam[RK_];
__device__ float g_c0[RK_];

// ---------------------------------------------------------------------------
// Prep: padded lambdas + c0[r,k] = lam[r,k] * <mean_r, bases_{r,k}>
// grid = R_, block = 128 (one thread per k)
// ---------------------------------------------------------------------------
__global__ void prep_kernel(const float* __restrict__ lambdas,
                            const float* __restrict__ bases,
                            const float* __restrict__ means,
                            const int*   __restrict__ lengths,
                            int total_lam) {
    int r = blockIdx.x;
    int k = threadIdx.x;

    __shared__ float smean[D_];
    for (int d = threadIdx.x; d < D_; d += blockDim.x)
        smean[d] = means[r * D_ + d];
    __syncthreads();

    int off = 0;
    for (int i = 0; i < r; i++) off += lengths[i];
    int len = lengths[r];

    float lam = 0.0f;
    if (k < len) {
        int idx = off + k;
        if (idx > total_lam - 1) idx = total_lam - 1;
        lam = lambdas[idx];
    }

    const float* brow = bases + ((size_t)r * K_ + k) * D_;
    float dot = 0.0f;
    #pragma unroll 8
    for (int d = 0; d < D_; d++) dot += smean[d] * brow[d];

    g_lam[r * K_ + k] = lam;
    g_c0[r * K_ + k]  = lam * dot;
}

// ---------------------------------------------------------------------------
// Ablated-slice sum: out[n,d] = sum_a x[n, abl[a], d]
// ---------------------------------------------------------------------------
__global__ void abl_kernel(const float* __restrict__ x,
                           const int* __restrict__ abl,
                           float* __restrict__ out) {
    __shared__ int sabl[ABL_];
    if (threadIdx.x < ABL_) sabl[threadIdx.x] = abl[threadIdx.x];
    __syncthreads();

    int idx = blockIdx.x * blockDim.x + threadIdx.x;  // 0 .. N_*D_-1
    int n = idx / D_;
    int d = idx - n * D_;
    const float* xp = x + (size_t)n * S_ * D_ + d;

    float s = 0.0f;
    #pragma unroll
    for (int a = 0; a < ABL_; a++)
        s += __ldg(xp + (size_t)sabl[a] * D_);
    out[idx] = s;
}

// ---------------------------------------------------------------------------
// GEMM1 (batched over r): coeffs[n, r*K+k] = lam[r,k]*(x[n,res_r,:] . bases[r,k,:]) - c0[r,k]
// Tiles: BM=64 (n), BN=64 (k), BK=16 (d). 256 threads, 4x4 micro-tile.
// grid = (N/64, K/64, R)
// ---------------------------------------------------------------------------
#define BM 64
#define BN 64
#define BK 16

__global__ __launch_bounds__(256, 4)
void gemm1_kernel(const float* __restrict__ x,
                  const float* __restrict__ bases,
                  const int* __restrict__ resid) {
    int r  = blockIdx.z;
    int n0 = blockIdx.x * BM;
    int k0 = blockIdx.y * BN;
    int s  = resid[r];

    const float* A = x + (size_t)s * D_;                 // + n*S_*D_ per row
    const float* B = bases + (size_t)r * K_ * D_;        // + k*D_ per row

    __shared__ float As[BK][BM + 4];
    __shared__ float Bs[BK][BN + 4];

    int tid  = threadIdx.x;
    int lrow = tid >> 2;          // 0..63
    int lc4  = (tid & 3) * 4;     // 0,4,8,12

    int tx = tid & 15;            // k direction
    int ty = tid >> 4;            // n direction

    float acc[4][4];
    #pragma unroll
    for (int i = 0; i < 4; i++)
        #pragma unroll
        for (int j = 0; j < 4; j++) acc[i][j] = 0.0f;

    for (int d0 = 0; d0 < D_; d0 += BK) {
        float4 av = *(const float4*)(A + (size_t)(n0 + lrow) * S_ * D_ + d0 + lc4);
        float4 bv = *(const float4*)(B + (size_t)(k0 + lrow) * D_       + d0 + lc4);
        As[lc4 + 0][lrow] = av.x; As[lc4 + 1][lrow] = av.y;
        As[lc4 + 2][lrow] = av.z; As[lc4 + 3][lrow] = av.w;
        Bs[lc4 + 0][lrow] = bv.x; Bs[lc4 + 1][lrow] = bv.y;
        Bs[lc4 + 2][lrow] = bv.z; Bs[lc4 + 3][lrow] = bv.w;
        __syncthreads();

        #pragma unroll
        for (int kk = 0; kk < BK; kk++) {
            float4 a = *(const float4*)&As[kk][ty * 4];
            float4 b = *(const float4*)&Bs[kk][tx * 4];
            float ar[4] = {a.x, a.y, a.z, a.w};
            float br[4] = {b.x, b.y, b.z, b.w};
            #pragma unroll
            for (int i = 0; i < 4; i++)
                #pragma unroll
                for (int j = 0; j < 4; j++)
                    acc[i][j] += ar[i] * br[j];
        }
        __syncthreads();
    }

    // epilogue: scale by lam, subtract c0, store to coeffs (N x RK, row major)
    #pragma unroll
    for (int i = 0; i < 4; i++) {
        int ng = n0 + ty * 4 + i;
        float4 v;
        float* vp = (float*)&v;
        #pragma unroll
        for (int j = 0; j < 4; j++) {
            int kg = k0 + tx * 4 + j;
            float lam = g_lam[r * K_ + kg];
            float c0  = g_c0[r * K_ + kg];
            vp[j] = lam * acc[i][j] - c0;
        }
        *(float4*)(g_coeffs + (size_t)ng * RK_ + r * K_ + k0 + tx * 4) = v;
    }
}

// ---------------------------------------------------------------------------
// GEMM2: out[n,d] += sum_j coeffs[n,j] * invb[j,d],  j in [0, RK_)
// grid = (N/64, D/64)
// ---------------------------------------------------------------------------
__global__ __launch_bounds__(256, 4)
void gemm2_kernel(const float* __restrict__ invb,
                  float* __restrict__ out) {
    int n0 = blockIdx.x * BM;
    int d0 = blockIdx.y * BN;

    __shared__ float As[BK][BM + 4];
    __shared__ float Bs[BK][BN + 4];

    int tid  = threadIdx.x;
    int lrow = tid >> 2;            // 0..63 (n rows for A)
    int lc4  = (tid & 3) * 4;       // j offset for A
    int jrow = tid >> 4;            // 0..15 (j rows for B)
    int dc4  = (tid & 15) * 4;      // d offset for B

    int tx = tid & 15;              // d direction
    int ty = tid >> 4;              // n direction

    float acc[4][4];
    #pragma unroll
    for (int i = 0; i < 4; i++)
        #pragma unroll
        for (int j = 0; j < 4; j++) acc[i][j] = 0.0f;

    for (int j0 = 0; j0 < RK_; j0 += BK) {
        float4 av = *(const float4*)(g_coeffs + (size_t)(n0 + lrow) * RK_ + j0 + lc4);
        As[lc4 + 0][lrow] = av.x; As[lc4 + 1][lrow] = av.y;
        As[lc4 + 2][lrow] = av.z; As[lc4 + 3][lrow] = av.w;
        float4 bv = *(const float4*)(invb + (size_t)(j0 + jrow) * D_ + d0 + dc4);
        *(float4*)&Bs[jrow][dc4] = bv;
        __syncthreads();

        #pragma unroll
        for (int kk = 0; kk < BK; kk++) {
            float4 a = *(const float4*)&As[kk][ty * 4];
            float4 b = *(const float4*)&Bs[kk][tx * 4];
            float ar[4] = {a.x, a.y, a.z, a.w};
            float br[4] = {b.x, b.y, b.z, b.w};
            #pragma unroll
            for (int i = 0; i < 4; i++)
                #pragma unroll
                for (int j = 0; j < 4; j++)
                    acc[i][j] += ar[i] * br[j];
        }
        __syncthreads();
    }

    // epilogue: accumulate onto out (already holds ablated sum)
    #pragma unroll
    for (int i = 0; i < 4; i++) {
        int ng = n0 + ty * 4 + i;
        float* op = out + (size_t)ng * D_ + d0 + tx * 4;
        float4 prev = *(float4*)op;
        prev.x += acc[i][0]; prev.y += acc[i][1];
        prev.z += acc[i][2]; prev.w += acc[i][3];
        *(float4*)op = prev;
    }
}

// ---------------------------------------------------------------------------
// Launch
// ---------------------------------------------------------------------------
extern "C" void kernel_launch(void* const* d_in, const int* in_sizes, int n_in,
                              void* d_out, int out_size) {
    const float* x       = (const float*)d_in[0];
    const float* lambdas = (const float*)d_in[1];
    const float* bases   = (const float*)d_in[2];
    const float* invb    = (const float*)d_in[3];
    const float* means   = (const float*)d_in[4];
    const int*   resid   = (const int*)d_in[5];   // int32 (JAX default x64-disabled)
    const int*   abl     = (const int*)d_in[6];   // int32
    const int*   lengths = (const int*)d_in[7];
    float*       out     = (float*)d_out;

    int total_lam = in_sizes[1];

    prep_kernel<<<R_, 128>>>(lambdas, bases, means, lengths, total_lam);
    abl_kernel<<<(N_ * D_) / 256, 256>>>(x, abl, out);
    gemm1_kernel<<<dim3(N_ / BM, K_ / BN, R_), 256>>>(x, bases, resid);
    gemm2_kernel<<<dim3(N_ / BM, D_ / BN), 256>>>(invb, out);
}

// round 7
// speedup vs baseline: 3.9142x; 3.9142x over previous
#include <cuda_runtime.h>
#include <cuda_bf16.h>
#include <cstdint>

#define N_   1024
#define S_   144
#define R_   96
#define K_   128
#define D_   768
#define ABL_ 48
#define RK_  (R_ * K_)   // 12288
#define KSPLIT 8

// ---------------------------------------------------------------------------
// Device-global scratch (no allocation allowed in kernel_launch)
// ---------------------------------------------------------------------------
__device__ float g_lam[RK_];
__device__ float g_c0[RK_];
__device__ __align__(16) __nv_bfloat16 g_xh [(size_t)R_ * N_ * D_];  // x gather hi [r][n][d]
__device__ __align__(16) __nv_bfloat16 g_xl [(size_t)R_ * N_ * D_];  // x gather lo
__device__ __align__(16) __nv_bfloat16 g_blh[(size_t)R_ * K_ * D_];  // bases*lam hi [rk][d]
__device__ __align__(16) __nv_bfloat16 g_bll[(size_t)R_ * K_ * D_];
__device__ __align__(16) __nv_bfloat16 g_chi[(size_t)N_ * RK_];      // coeffs hi [n][rk]
__device__ __align__(16) __nv_bfloat16 g_clo[(size_t)N_ * RK_];
__device__ __align__(16) __nv_bfloat16 g_ibth[(size_t)D_ * RK_];     // invb^T hi [d][j]
__device__ __align__(16) __nv_bfloat16 g_ibtl[(size_t)D_ * RK_];
__device__ float g_part[(size_t)KSPLIT * N_ * D_];

// ---------------------------------------------------------------------------
// Helpers (base-ISA only: cp.async / ldmatrix / mma.sync — no tcgen05)
// ---------------------------------------------------------------------------
__device__ __forceinline__ uint32_t smem_u32(const void* p) {
    uint32_t a;
    asm("{ .reg .u64 t; cvta.to.shared.u64 t, %1; cvt.u32.u64 %0, t; }"
        : "=r"(a) : "l"(p));
    return a;
}

__device__ __forceinline__ void cp16(uint32_t dst, const void* src) {
    asm volatile("cp.async.cg.shared.global [%0], [%1], 16;" :: "r"(dst), "l"(src));
}
#define CP_COMMIT() asm volatile("cp.async.commit_group;" ::: "memory")
#define CP_WAIT1()  asm volatile("cp.async.wait_group 1;"  ::: "memory")

__device__ __forceinline__ void ldsm4(uint32_t* r, uint32_t a) {
    asm volatile("ldmatrix.sync.aligned.m8n8.x4.shared.b16 {%0,%1,%2,%3}, [%4];"
        : "=r"(r[0]), "=r"(r[1]), "=r"(r[2]), "=r"(r[3]) : "r"(a));
}

__device__ __forceinline__ void mma_bf16(float* d, const uint32_t* a, const uint32_t* b) {
    asm volatile(
        "mma.sync.aligned.m16n8k16.row.col.f32.bf16.bf16.f32 "
        "{%0,%1,%2,%3}, {%4,%5,%6,%7}, {%8,%9}, {%0,%1,%2,%3};"
        : "+f"(d[0]), "+f"(d[1]), "+f"(d[2]), "+f"(d[3])
        : "r"(a[0]), "r"(a[1]), "r"(a[2]), "r"(a[3]), "r"(b[0]), "r"(b[1]));
}

__device__ __forceinline__ void split1(float v, __nv_bfloat16& h, __nv_bfloat16& l) {
    h = __float2bfloat16(v);
    l = __float2bfloat16(v - __bfloat162float(h));
}
__device__ __forceinline__ uint32_t pack2(__nv_bfloat16 a, __nv_bfloat16 b) {
    uint16_t x = *(uint16_t*)&a, y = *(uint16_t*)&b;
    return (uint32_t)x | ((uint32_t)y << 16);
}

// smem tile: 128 rows x 32 bf16 (64B rows), 16B-chunk swizzle: phys = ch ^ ((row>>1)&3)
#define TILE_BYTES 8192
#define STG_BYTES  32768   // Ah | Al | Bh | Bl
#define NSTG 3
#define SMEM_TOTAL (NSTG * STG_BYTES)

// ---------------------------------------------------------------------------
// Small kernels
// ---------------------------------------------------------------------------
__global__ void prep_kernel(const float* __restrict__ lambdas,
                            const float* __restrict__ bases,
                            const float* __restrict__ means,
                            const int*   __restrict__ lengths,
                            int total_lam) {
    int r = blockIdx.x;
    int k = threadIdx.x;

    __shared__ float smean[D_];
    for (int d = threadIdx.x; d < D_; d += blockDim.x)
        smean[d] = means[r * D_ + d];
    __syncthreads();

    int off = 0;
    for (int i = 0; i < r; i++) off += lengths[i];
    int len = lengths[r];

    float lam = 0.0f;
    if (k < len) {
        int idx = off + k;
        if (idx > total_lam - 1) idx = total_lam - 1;
        lam = lambdas[idx];
    }

    const float* brow = bases + ((size_t)r * K_ + k) * D_;
    float dot = 0.0f;
    #pragma unroll 8
    for (int d = 0; d < D_; d++) dot += smean[d] * brow[d];

    g_lam[r * K_ + k] = lam;
    g_c0[r * K_ + k]  = lam * dot;
}

// gather + split x residual slots: [r][n][d] bf16 hi/lo
__global__ void convert_x(const float* __restrict__ x, const int* __restrict__ resid) {
    int r = blockIdx.y;
    int s = resid[r];
    size_t off = ((size_t)blockIdx.x * blockDim.x + threadIdx.x) * 4;  // within n*d plane
    int n = (int)(off / D_);
    int d = (int)(off % D_);
    float4 v = *(const float4*)(x + ((size_t)n * S_ + s) * D_ + d);
    __align__(8) __nv_bfloat16 h[4], l[4];
    split1(v.x, h[0], l[0]); split1(v.y, h[1], l[1]);
    split1(v.z, h[2], l[2]); split1(v.w, h[3], l[3]);
    size_t o = ((size_t)r * N_ + n) * D_ + d;
    *(uint2*)(g_xh + o) = *(uint2*)h;
    *(uint2*)(g_xl + o) = *(uint2*)l;
}

// bases*lam -> bf16 hi/lo
__global__ void convert_blam(const float* __restrict__ bases) {
    size_t i = ((size_t)blockIdx.x * blockDim.x + threadIdx.x) * 4;
    int rk = (int)(i / D_);
    float lam = g_lam[rk];
    float4 v = *(const float4*)(bases + i);
    __align__(8) __nv_bfloat16 h[4], l[4];
    split1(v.x * lam, h[0], l[0]); split1(v.y * lam, h[1], l[1]);
    split1(v.z * lam, h[2], l[2]); split1(v.w * lam, h[3], l[3]);
    *(uint2*)(g_blh + i) = *(uint2*)h;
    *(uint2*)(g_bll + i) = *(uint2*)l;
}

// invb [j][d] -> transposed bf16 hi/lo [d][j]
__global__ void convert_ibt(const float* __restrict__ invb) {
    __shared__ float t[32][33];
    int jb = blockIdx.x * 32, db = blockIdx.y * 32;
    int tx = threadIdx.x, ty = threadIdx.y;  // 32 x 8
    #pragma unroll
    for (int k = 0; k < 4; k++)
        t[ty + 8 * k][tx] = invb[(size_t)(jb + ty + 8 * k) * D_ + db + tx];
    __syncthreads();
    #pragma unroll
    for (int k = 0; k < 4; k++) {
        float v = t[tx][ty + 8 * k];
        __nv_bfloat16 h, l;
        split1(v, h, l);
        size_t o = (size_t)(db + ty + 8 * k) * RK_ + jb + tx;
        g_ibth[o] = h;
        g_ibtl[o] = l;
    }
}

// ablated-slice sum
__global__ void abl_kernel(const float* __restrict__ x,
                           const int* __restrict__ abl,
                           float* __restrict__ out) {
    __shared__ int sabl[ABL_];
    if (threadIdx.x < ABL_) sabl[threadIdx.x] = abl[threadIdx.x];
    __syncthreads();

    int idx = blockIdx.x * blockDim.x + threadIdx.x;
    int n = idx / D_;
    int d = idx - n * D_;
    const float* xp = x + (size_t)n * S_ * D_ + d;

    float s = 0.0f;
    #pragma unroll
    for (int a = 0; a < ABL_; a++)
        s += __ldg(xp + (size_t)sabl[a] * D_);
    out[idx] = s;
}

// ---------------------------------------------------------------------------
// GEMM1 (mma.sync bf16x3): coeffs[n, r*K+k] = x_split[r,n,:] . blam[r,k,:] - c0
// Block 128(m=n) x 128(n=k) x BK=32(d). grid=(8, 96), 256 thr, 8 warps 2x4.
// ---------------------------------------------------------------------------
__global__ __launch_bounds__(256)
void gemm1_mma(const int* __restrict__ dummy_unused) {
    extern __shared__ __align__(128) char sm[];
    uint32_t sbase = smem_u32(sm);
    int tid = threadIdx.x, lane = tid & 31, wid = tid >> 5;
    int r = blockIdx.y, n0 = blockIdx.x * 128;
    int wm = (wid >> 2) * 64, wn = (wid & 3) * 32;

    const __nv_bfloat16* Ah = g_xh  + ((size_t)r * N_ + n0) * D_;
    const __nv_bfloat16* Al = g_xl  + ((size_t)r * N_ + n0) * D_;
    const __nv_bfloat16* Bh = g_blh + (size_t)r * K_ * D_;
    const __nv_bfloat16* Bl = g_bll + (size_t)r * K_ * D_;

    float acc[4][4][4];
    #pragma unroll
    for (int a = 0; a < 4; a++)
        #pragma unroll
        for (int b = 0; b < 4; b++)
            #pragma unroll
            for (int c = 0; c < 4; c++) acc[a][b][c] = 0.0f;

    int frow = tid >> 2, fch = tid & 3;

    auto fill = [&](int c, int s) {
        uint32_t b = sbase + s * STG_BYTES;
        int d0 = c * 32;
        #pragma unroll
        for (int i = 0; i < 2; i++) {
            int rw = frow + 64 * i;
            uint32_t off = rw * 64 + ((fch ^ ((rw >> 1) & 3)) << 4);
            size_t so = (size_t)rw * D_ + d0 + fch * 8;
            cp16(b +                  off, Ah + so);
            cp16(b +     TILE_BYTES + off, Al + so);
            cp16(b + 2 * TILE_BYTES + off, Bh + so);
            cp16(b + 3 * TILE_BYTES + off, Bl + so);
        }
    };

    auto compute = [&](int s) {
        uint32_t b = sbase + s * STG_BYTES;
        #pragma unroll
        for (int kk = 0; kk < 2; kk++) {
            int lc = kk * 2 + (lane >> 4);
            uint32_t ah[4][4], al[4][4];
            #pragma unroll
            for (int mi = 0; mi < 4; mi++) {
                int rw = wm + mi * 16 + (lane & 15);
                uint32_t off = rw * 64 + ((lc ^ ((rw >> 1) & 3)) << 4);
                ldsm4(ah[mi], b + off);
                ldsm4(al[mi], b + TILE_BYTES + off);
            }
            uint32_t bh[4][2], bl[4][2];
            #pragma unroll
            for (int bi = 0; bi < 2; bi++) {
                int rw = wn + bi * 16 + (lane & 15);
                uint32_t off = rw * 64 + ((lc ^ ((rw >> 1) & 3)) << 4);
                uint32_t t[4];
                ldsm4(t, b + 2 * TILE_BYTES + off);
                bh[2*bi][0] = t[0]; bh[2*bi][1] = t[2];
                bh[2*bi+1][0] = t[1]; bh[2*bi+1][1] = t[3];
                ldsm4(t, b + 3 * TILE_BYTES + off);
                bl[2*bi][0] = t[0]; bl[2*bi][1] = t[2];
                bl[2*bi+1][0] = t[1]; bl[2*bi+1][1] = t[3];
            }
            #pragma unroll
            for (int mi = 0; mi < 4; mi++)
                #pragma unroll
                for (int ni = 0; ni < 4; ni++) {
                    mma_bf16(acc[mi][ni], ah[mi], bh[ni]);
                    mma_bf16(acc[mi][ni], ah[mi], bl[ni]);
                    mma_bf16(acc[mi][ni], al[mi], bh[ni]);
                }
        }
    };

    fill(0, 0); CP_COMMIT();
    fill(1, 1); CP_COMMIT();
    #pragma unroll 1
    for (int c = 0; c < 24; c++) {
        CP_WAIT1();
        __syncthreads();
        if (c + 2 < 24) { fill(c + 2, (c + 2) % NSTG); CP_COMMIT(); }
        compute(c % NSTG);
    }

    // epilogue: subtract c0, split, store coeffs bf16 hi/lo
    int mrow = lane >> 2, kcol = (lane & 3) * 2;
    #pragma unroll
    for (int mi = 0; mi < 4; mi++)
        #pragma unroll
        for (int ni = 0; ni < 4; ni++) {
            int kg = wn + ni * 8 + kcol;
            float c00 = g_c0[r * K_ + kg], c01 = g_c0[r * K_ + kg + 1];
            int m0 = n0 + wm + mi * 16 + mrow;
            #pragma unroll
            for (int half = 0; half < 2; half++) {
                float v0 = acc[mi][ni][half * 2 + 0] - c00;
                float v1 = acc[mi][ni][half * 2 + 1] - c01;
                __nv_bfloat16 h0, l0, h1, l1;
                split1(v0, h0, l0);
                split1(v1, h1, l1);
                size_t o = (size_t)(m0 + half * 8) * RK_ + r * K_ + kg;
                *(uint32_t*)(g_chi + o) = pack2(h0, h1);
                *(uint32_t*)(g_clo + o) = pack2(l0, l1);
            }
        }
}

// ---------------------------------------------------------------------------
// GEMM2 (mma.sync bf16x3): part[ks][n][d] = sum_j coeffs[n,j] * invbT[d,j]
// Block 128(n) x 128(d) x BK=32(j), K-chunk=1536/split. grid=(8, 6, KSPLIT).
// ---------------------------------------------------------------------------
__global__ __launch_bounds__(256)
void gemm2_mma() {
    extern __shared__ __align__(128) char sm[];
    uint32_t sbase = smem_u32(sm);
    int tid = threadIdx.x, lane = tid & 31, wid = tid >> 5;
    int n0 = blockIdx.x * 128, d0 = blockIdx.y * 128, ks = blockIdx.z;
    int jbase = ks * (RK_ / KSPLIT);   // 1536 per split
    int wm = (wid >> 2) * 64, wn = (wid & 3) * 32;

    const __nv_bfloat16* Ah = g_chi  + (size_t)n0 * RK_ + jbase;
    const __nv_bfloat16* Al = g_clo  + (size_t)n0 * RK_ + jbase;
    const __nv_bfloat16* Bh = g_ibth + (size_t)d0 * RK_ + jbase;
    const __nv_bfloat16* Bl = g_ibtl + (size_t)d0 * RK_ + jbase;

    float acc[4][4][4];
    #pragma unroll
    for (int a = 0; a < 4; a++)
        #pragma unroll
        for (int b = 0; b < 4; b++)
            #pragma unroll
            for (int c = 0; c < 4; c++) acc[a][b][c] = 0.0f;

    int frow = tid >> 2, fch = tid & 3;

    auto fill = [&](int c, int s) {
        uint32_t b = sbase + s * STG_BYTES;
        int j0 = c * 32;
        #pragma unroll
        for (int i = 0; i < 2; i++) {
            int rw = frow + 64 * i;
            uint32_t off = rw * 64 + ((fch ^ ((rw >> 1) & 3)) << 4);
            size_t so = (size_t)rw * RK_ + j0 + fch * 8;
            cp16(b +                  off, Ah + so);
            cp16(b +     TILE_BYTES + off, Al + so);
            cp16(b + 2 * TILE_BYTES + off, Bh + so);
            cp16(b + 3 * TILE_BYTES + off, Bl + so);
        }
    };

    auto compute = [&](int s) {
        uint32_t b = sbase + s * STG_BYTES;
        #pragma unroll
        for (int kk = 0; kk < 2; kk++) {
            int lc = kk * 2 + (lane >> 4);
            uint32_t ah[4][4], al[4][4];
            #pragma unroll
            for (int mi = 0; mi < 4; mi++) {
                int rw = wm + mi * 16 + (lane & 15);
                uint32_t off = rw * 64 + ((lc ^ ((rw >> 1) & 3)) << 4);
                ldsm4(ah[mi], b + off);
                ldsm4(al[mi], b + TILE_BYTES + off);
            }
            uint32_t bh[4][2], bl[4][2];
            #pragma unroll
            for (int bi = 0; bi < 2; bi++) {
                int rw = wn + bi * 16 + (lane & 15);
                uint32_t off = rw * 64 + ((lc ^ ((rw >> 1) & 3)) << 4);
                uint32_t t[4];
                ldsm4(t, b + 2 * TILE_BYTES + off);
                bh[2*bi][0] = t[0]; bh[2*bi][1] = t[2];
                bh[2*bi+1][0] = t[1]; bh[2*bi+1][1] = t[3];
                ldsm4(t, b + 3 * TILE_BYTES + off);
                bl[2*bi][0] = t[0]; bl[2*bi][1] = t[2];
                bl[2*bi+1][0] = t[1]; bl[2*bi+1][1] = t[3];
            }
            #pragma unroll
            for (int mi = 0; mi < 4; mi++)
                #pragma unroll
                for (int ni = 0; ni < 4; ni++) {
                    mma_bf16(acc[mi][ni], ah[mi], bh[ni]);
                    mma_bf16(acc[mi][ni], ah[mi], bl[ni]);
                    mma_bf16(acc[mi][ni], al[mi], bh[ni]);
                }
        }
    };

    const int NC = (RK_ / KSPLIT) / 32;   // 48
    fill(0, 0); CP_COMMIT();
    fill(1, 1); CP_COMMIT();
    #pragma unroll 1
    for (int c = 0; c < NC; c++) {
        CP_WAIT1();
        __syncthreads();
        if (c + 2 < NC) { fill(c + 2, (c + 2) % NSTG); CP_COMMIT(); }
        compute(c % NSTG);
    }

    // epilogue: fp32 partials
    int mrow = lane >> 2, kcol = (lane & 3) * 2;
    #pragma unroll
    for (int mi = 0; mi < 4; mi++)
        #pragma unroll
        for (int ni = 0; ni < 4; ni++) {
            int dg = d0 + wn + ni * 8 + kcol;
            int m0 = n0 + wm + mi * 16 + mrow;
            #pragma unroll
            for (int half = 0; half < 2; half++) {
                float2 v = make_float2(acc[mi][ni][half * 2 + 0],
                                       acc[mi][ni][half * 2 + 1]);
                *(float2*)(g_part + ((size_t)ks * N_ + m0 + half * 8) * D_ + dg) = v;
            }
        }
}

// out += sum of KSPLIT partials
__global__ void reduce_out(float* __restrict__ out) {
    size_t i = ((size_t)blockIdx.x * blockDim.x + threadIdx.x) * 4;
    float4 o = *(float4*)(out + i);
    #pragma unroll
    for (int s = 0; s < KSPLIT; s++) {
        float4 p = *(const float4*)(g_part + (size_t)s * N_ * D_ + i);
        o.x += p.x; o.y += p.y; o.z += p.z; o.w += p.w;
    }
    *(float4*)(out + i) = o;
}

// ---------------------------------------------------------------------------
// Launch
// ---------------------------------------------------------------------------
extern "C" void kernel_launch(void* const* d_in, const int* in_sizes, int n_in,
                              void* d_out, int out_size) {
    const float* x       = (const float*)d_in[0];
    const float* lambdas = (const float*)d_in[1];
    const float* bases   = (const float*)d_in[2];
    const float* invb    = (const float*)d_in[3];
    const float* means   = (const float*)d_in[4];
    const int*   resid   = (const int*)d_in[5];
    const int*   abl     = (const int*)d_in[6];
    const int*   lengths = (const int*)d_in[7];
    float*       out     = (float*)d_out;

    int total_lam = in_sizes[1];

    cudaFuncSetAttribute(gemm1_mma, cudaFuncAttributeMaxDynamicSharedMemorySize, SMEM_TOTAL);
    cudaFuncSetAttribute(gemm2_mma, cudaFuncAttributeMaxDynamicSharedMemorySize, SMEM_TOTAL);

    prep_kernel<<<R_, 128>>>(lambdas, bases, means, lengths, total_lam);
    convert_blam<<<(R_ * K_ * D_ / 4) / 256, 256>>>(bases);
    convert_ibt<<<dim3(RK_ / 32, D_ / 32), dim3(32, 8)>>>(invb);
    convert_x<<<dim3((N_ * D_ / 4) / 256, R_), 256>>>(x, resid);
    abl_kernel<<<(N_ * D_) / 256, 256>>>(x, abl, out);
    gemm1_mma<<<dim3(N_ / 128, R_), 256, SMEM_TOTAL>>>(resid);
    gemm2_mma<<<dim3(N_ / 128, D_ / 128, KSPLIT), 256, SMEM_TOTAL>>>();
    reduce_out<<<(N_ * D_ / 4) / 256, 256>>>(out);
}

// round 8
// speedup vs baseline: 4.6278x; 1.1823x over previous
#include <cuda_runtime.h>
#include <cuda_bf16.h>
#include <cstdint>

#define N_   1024
#define S_   144
#define R_   96
#define K_   128
#define D_   768
#define ABL_ 48
#define RK_  (R_ * K_)   // 12288
#define KSPLIT 8

// ---------------------------------------------------------------------------
// Device-global scratch (no allocation allowed in kernel_launch)
// ---------------------------------------------------------------------------
__device__ float g_lam[RK_];
__device__ float g_c0[RK_];
__device__ __align__(16) __nv_bfloat16 g_blh[(size_t)R_ * K_ * D_];  // bases*lam hi [rk][d]
__device__ __align__(16) __nv_bfloat16 g_bll[(size_t)R_ * K_ * D_];
__device__ __align__(16) __nv_bfloat16 g_chi[(size_t)N_ * RK_];      // coeffs hi [n][rk]
__device__ __align__(16) __nv_bfloat16 g_clo[(size_t)N_ * RK_];
__device__ __align__(16) __nv_bfloat16 g_ibth[(size_t)D_ * RK_];     // invb^T hi [d][j]
__device__ __align__(16) __nv_bfloat16 g_ibtl[(size_t)D_ * RK_];
__device__ float g_part[(size_t)KSPLIT * N_ * D_];

// ---------------------------------------------------------------------------
// Helpers (base-ISA only: cp.async / ldmatrix / mma.sync — no tcgen05)
// ---------------------------------------------------------------------------
__device__ __forceinline__ uint32_t smem_u32(const void* p) {
    uint32_t a;
    asm("{ .reg .u64 t; cvta.to.shared.u64 t, %1; cvt.u32.u64 %0, t; }"
        : "=r"(a) : "l"(p));
    return a;
}

__device__ __forceinline__ void cp16(uint32_t dst, const void* src) {
    asm volatile("cp.async.cg.shared.global [%0], [%1], 16;" :: "r"(dst), "l"(src));
}
#define CP_COMMIT() asm volatile("cp.async.commit_group;" ::: "memory")
#define CP_WAIT1()  asm volatile("cp.async.wait_group 1;"  ::: "memory")

__device__ __forceinline__ void ldsm4(uint32_t* r, uint32_t a) {
    asm volatile("ldmatrix.sync.aligned.m8n8.x4.shared.b16 {%0,%1,%2,%3}, [%4];"
        : "=r"(r[0]), "=r"(r[1]), "=r"(r[2]), "=r"(r[3]) : "r"(a));
}

__device__ __forceinline__ void mma_bf16(float* d, const uint32_t* a, const uint32_t* b) {
    asm volatile(
        "mma.sync.aligned.m16n8k16.row.col.f32.bf16.bf16.f32 "
        "{%0,%1,%2,%3}, {%4,%5,%6,%7}, {%8,%9}, {%0,%1,%2,%3};"
        : "+f"(d[0]), "+f"(d[1]), "+f"(d[2]), "+f"(d[3])
        : "r"(a[0]), "r"(a[1]), "r"(a[2]), "r"(a[3]), "r"(b[0]), "r"(b[1]));
}

__device__ __forceinline__ void split1(float v, __nv_bfloat16& h, __nv_bfloat16& l) {
    h = __float2bfloat16(v);
    l = __float2bfloat16(v - __bfloat162float(h));
}
__device__ __forceinline__ uint32_t pack2(__nv_bfloat16 a, __nv_bfloat16 b) {
    uint16_t x = *(uint16_t*)&a, y = *(uint16_t*)&b;
    return (uint32_t)x | ((uint32_t)y << 16);
}

// smem tile: 128 rows x 32 bf16 (64B rows), 16B-chunk swizzle: phys = ch ^ ((row>>1)&3)
#define TILE_BYTES 8192
#define STG_BYTES  32768   // Ah | Al | Bh | Bl
#define NSTG 3
#define SMEM_TOTAL (NSTG * STG_BYTES)

// ---------------------------------------------------------------------------
// Small kernels
// ---------------------------------------------------------------------------
__global__ void prep_kernel(const float* __restrict__ lambdas,
                            const float* __restrict__ bases,
                            const float* __restrict__ means,
                            const int*   __restrict__ lengths,
                            int total_lam) {
    int r = blockIdx.x;
    int k = threadIdx.x;

    __shared__ float smean[D_];
    for (int d = threadIdx.x; d < D_; d += blockDim.x)
        smean[d] = means[r * D_ + d];
    __syncthreads();

    int off = 0;
    for (int i = 0; i < r; i++) off += lengths[i];
    int len = lengths[r];

    float lam = 0.0f;
    if (k < len) {
        int idx = off + k;
        if (idx > total_lam - 1) idx = total_lam - 1;
        lam = lambdas[idx];
    }

    const float* brow = bases + ((size_t)r * K_ + k) * D_;
    float dot = 0.0f;
    #pragma unroll 8
    for (int d = 0; d < D_; d++) dot += smean[d] * brow[d];

    g_lam[r * K_ + k] = lam;
    g_c0[r * K_ + k]  = lam * dot;
}

// bases*lam -> bf16 hi/lo
__global__ void convert_blam(const float* __restrict__ bases) {
    size_t i = ((size_t)blockIdx.x * blockDim.x + threadIdx.x) * 4;
    int rk = (int)(i / D_);
    float lam = g_lam[rk];
    float4 v = *(const float4*)(bases + i);
    __align__(8) __nv_bfloat16 h[4], l[4];
    split1(v.x * lam, h[0], l[0]); split1(v.y * lam, h[1], l[1]);
    split1(v.z * lam, h[2], l[2]); split1(v.w * lam, h[3], l[3]);
    *(uint2*)(g_blh + i) = *(uint2*)h;
    *(uint2*)(g_bll + i) = *(uint2*)l;
}

// invb [j][d] -> transposed bf16 hi/lo [d][j]
__global__ void convert_ibt(const float* __restrict__ invb) {
    __shared__ float t[32][33];
    int jb = blockIdx.x * 32, db = blockIdx.y * 32;
    int tx = threadIdx.x, ty = threadIdx.y;  // 32 x 8
    #pragma unroll
    for (int k = 0; k < 4; k++)
        t[ty + 8 * k][tx] = invb[(size_t)(jb + ty + 8 * k) * D_ + db + tx];
    __syncthreads();
    #pragma unroll
    for (int k = 0; k < 4; k++) {
        float v = t[tx][ty + 8 * k];
        __nv_bfloat16 h, l;
        split1(v, h, l);
        size_t o = (size_t)(db + ty + 8 * k) * RK_ + jb + tx;
        g_ibth[o] = h;
        g_ibtl[o] = l;
    }
}

// ablated-slice sum
__global__ void abl_kernel(const float* __restrict__ x,
                           const int* __restrict__ abl,
                           float* __restrict__ out) {
    __shared__ int sabl[ABL_];
    if (threadIdx.x < ABL_) sabl[threadIdx.x] = abl[threadIdx.x];
    __syncthreads();

    int idx = blockIdx.x * blockDim.x + threadIdx.x;
    int n = idx / D_;
    int d = idx - n * D_;
    const float* xp = x + (size_t)n * S_ * D_ + d;

    float s = 0.0f;
    #pragma unroll
    for (int a = 0; a < ABL_; a++)
        s += __ldg(xp + (size_t)sabl[a] * D_);
    out[idx] = s;
}

// ---------------------------------------------------------------------------
// GEMM1 (mma.sync bf16x3, FUSED x gather+split in fill):
//   coeffs[n, r*K+k] = x[n, s_r, :] . blam[r,k,:] - c0[r,k]
// Block 128(m=n) x 128(n=k) x BK=32(d). grid=(8, 96), 256 thr, 8 warps 2x4.
// A: LDG fp32 -> reg split -> swizzled STS (pipelined one iter ahead)
// B: cp.async of pre-split bf16
// ---------------------------------------------------------------------------
#define G1_NC 24

__global__ __launch_bounds__(256)
void gemm1_mma(const float* __restrict__ x, const int* __restrict__ resid) {
    extern __shared__ __align__(128) char sm[];
    uint32_t sbase = smem_u32(sm);
    int tid = threadIdx.x, lane = tid & 31, wid = tid >> 5;
    int r = blockIdx.y, n0 = blockIdx.x * 128;
    int s = __ldg(resid + r);
    int wm = (wid >> 2) * 64, wn = (wid & 3) * 32;

    const float* Ax = x + ((size_t)n0 * S_ + s) * D_;   // + rw*S_*D_ per row
    const __nv_bfloat16* Bh = g_blh + (size_t)r * K_ * D_;
    const __nv_bfloat16* Bl = g_bll + (size_t)r * K_ * D_;

    float acc[4][4][4];
    #pragma unroll
    for (int a = 0; a < 4; a++)
        #pragma unroll
        for (int b = 0; b < 4; b++)
            #pragma unroll
            for (int c = 0; c < 4; c++) acc[a][b][c] = 0.0f;

    int frow = tid >> 2, fch = tid & 3;

    // A reg buffer: 2 rows x 8 floats = 4 float4
    float4 ra[4];

    auto ldgA = [&](int c) {
        int d0 = c * 32;
        #pragma unroll
        for (int i = 0; i < 2; i++) {
            int rw = frow + 64 * i;
            const float* p = Ax + (size_t)rw * (S_ * D_) + d0 + fch * 8;
            ra[2 * i]     = __ldg((const float4*)p);
            ra[2 * i + 1] = __ldg((const float4*)(p + 4));
        }
    };

    auto stsA = [&](int stg) {
        char* b = sm + stg * STG_BYTES;
        #pragma unroll
        for (int i = 0; i < 2; i++) {
            int rw = frow + 64 * i;
            uint32_t off = rw * 64 + ((fch ^ ((rw >> 1) & 3)) << 4);
            float vv[8] = {ra[2*i].x, ra[2*i].y, ra[2*i].z, ra[2*i].w,
                           ra[2*i+1].x, ra[2*i+1].y, ra[2*i+1].z, ra[2*i+1].w};
            __align__(16) __nv_bfloat16 h[8], l[8];
            #pragma unroll
            for (int j = 0; j < 8; j++) split1(vv[j], h[j], l[j]);
            *(uint4*)(b + off)              = *(uint4*)h;
            *(uint4*)(b + TILE_BYTES + off) = *(uint4*)l;
        }
    };

    auto cpB = [&](int c, int stg) {
        uint32_t b = sbase + stg * STG_BYTES;
        int d0 = c * 32;
        #pragma unroll
        for (int i = 0; i < 2; i++) {
            int rw = frow + 64 * i;
            uint32_t off = rw * 64 + ((fch ^ ((rw >> 1) & 3)) << 4);
            size_t so = (size_t)rw * D_ + d0 + fch * 8;
            cp16(b + 2 * TILE_BYTES + off, Bh + so);
            cp16(b + 3 * TILE_BYTES + off, Bl + so);
        }
    };

    auto compute = [&](int stg) {
        uint32_t b = sbase + stg * STG_BYTES;
        #pragma unroll
        for (int kk = 0; kk < 2; kk++) {
            int lc = kk * 2 + (lane >> 4);
            uint32_t ah[4][4], al[4][4];
            #pragma unroll
            for (int mi = 0; mi < 4; mi++) {
                int rw = wm + mi * 16 + (lane & 15);
                uint32_t off = rw * 64 + ((lc ^ ((rw >> 1) & 3)) << 4);
                ldsm4(ah[mi], b + off);
                ldsm4(al[mi], b + TILE_BYTES + off);
            }
            uint32_t bh[4][2], bl[4][2];
            #pragma unroll
            for (int bi = 0; bi < 2; bi++) {
                int rw = wn + bi * 16 + (lane & 15);
                uint32_t off = rw * 64 + ((lc ^ ((rw >> 1) & 3)) << 4);
                uint32_t t[4];
                ldsm4(t, b + 2 * TILE_BYTES + off);
                bh[2*bi][0] = t[0]; bh[2*bi][1] = t[2];
                bh[2*bi+1][0] = t[1]; bh[2*bi+1][1] = t[3];
                ldsm4(t, b + 3 * TILE_BYTES + off);
                bl[2*bi][0] = t[0]; bl[2*bi][1] = t[2];
                bl[2*bi+1][0] = t[1]; bl[2*bi+1][1] = t[3];
            }
            #pragma unroll
            for (int mi = 0; mi < 4; mi++)
                #pragma unroll
                for (int ni = 0; ni < 4; ni++) {
                    mma_bf16(acc[mi][ni], ah[mi], bh[ni]);
                    mma_bf16(acc[mi][ni], ah[mi], bl[ni]);
                    mma_bf16(acc[mi][ni], al[mi], bh[ni]);
                }
        }
    };

    // prologue: stages 0,1 fully filled; LDG for chunk 2 in flight
    ldgA(0); stsA(0); cpB(0, 0); CP_COMMIT();
    ldgA(1); stsA(1); cpB(1, 1); CP_COMMIT();
    ldgA(2);

    #pragma unroll 1
    for (int c = 0; c < G1_NC; c++) {
        CP_WAIT1();
        __syncthreads();
        if (c + 2 < G1_NC) {
            int stg = (c + 2) % NSTG;
            stsA(stg);                 // regs from ldgA(c+2), landed during compute(c-1)
            cpB(c + 2, stg); CP_COMMIT();
            if (c + 3 < G1_NC) ldgA(c + 3);
        }
        compute(c % NSTG);
    }

    // epilogue: subtract c0, split, store coeffs bf16 hi/lo
    int mrow = lane >> 2, kcol = (lane & 3) * 2;
    #pragma unroll
    for (int mi = 0; mi < 4; mi++)
        #pragma unroll
        for (int ni = 0; ni < 4; ni++) {
            int kg = wn + ni * 8 + kcol;
            float c00 = g_c0[r * K_ + kg], c01 = g_c0[r * K_ + kg + 1];
            int m0 = n0 + wm + mi * 16 + mrow;
            #pragma unroll
            for (int half = 0; half < 2; half++) {
                float v0 = acc[mi][ni][half * 2 + 0] - c00;
                float v1 = acc[mi][ni][half * 2 + 1] - c01;
                __nv_bfloat16 h0, l0, h1, l1;
                split1(v0, h0, l0);
                split1(v1, h1, l1);
                size_t o = (size_t)(m0 + half * 8) * RK_ + r * K_ + kg;
                *(uint32_t*)(g_chi + o) = pack2(h0, h1);
                *(uint32_t*)(g_clo + o) = pack2(l0, l1);
            }
        }
}

// ---------------------------------------------------------------------------
// GEMM2 (mma.sync bf16x3): part[ks][n][d] = sum_j coeffs[n,j] * invbT[d,j]
// Block 128(n) x 128(d) x BK=32(j), K-chunk=1536/split. grid=(8, 6, KSPLIT).
// ---------------------------------------------------------------------------
__global__ __launch_bounds__(256)
void gemm2_mma() {
    extern __shared__ __align__(128) char sm[];
    uint32_t sbase = smem_u32(sm);
    int tid = threadIdx.x, lane = tid & 31, wid = tid >> 5;
    int n0 = blockIdx.x * 128, d0 = blockIdx.y * 128, ks = blockIdx.z;
    int jbase = ks * (RK_ / KSPLIT);   // 1536 per split
    int wm = (wid >> 2) * 64, wn = (wid & 3) * 32;

    const __nv_bfloat16* Ah = g_chi  + (size_t)n0 * RK_ + jbase;
    const __nv_bfloat16* Al = g_clo  + (size_t)n0 * RK_ + jbase;
    const __nv_bfloat16* Bh = g_ibth + (size_t)d0 * RK_ + jbase;
    const __nv_bfloat16* Bl = g_ibtl + (size_t)d0 * RK_ + jbase;

    float acc[4][4][4];
    #pragma unroll
    for (int a = 0; a < 4; a++)
        #pragma unroll
        for (int b = 0; b < 4; b++)
            #pragma unroll
            for (int c = 0; c < 4; c++) acc[a][b][c] = 0.0f;

    int frow = tid >> 2, fch = tid & 3;

    auto fill = [&](int c, int stg) {
        uint32_t b = sbase + stg * STG_BYTES;
        int j0 = c * 32;
        #pragma unroll
        for (int i = 0; i < 2; i++) {
            int rw = frow + 64 * i;
            uint32_t off = rw * 64 + ((fch ^ ((rw >> 1) & 3)) << 4);
            size_t so = (size_t)rw * RK_ + j0 + fch * 8;
            cp16(b +                  off, Ah + so);
            cp16(b +     TILE_BYTES + off, Al + so);
            cp16(b + 2 * TILE_BYTES + off, Bh + so);
            cp16(b + 3 * TILE_BYTES + off, Bl + so);
        }
    };

    auto compute = [&](int stg) {
        uint32_t b = sbase + stg * STG_BYTES;
        #pragma unroll
        for (int kk = 0; kk < 2; kk++) {
            int lc = kk * 2 + (lane >> 4);
            uint32_t ah[4][4], al[4][4];
            #pragma unroll
            for (int mi = 0; mi < 4; mi++) {
                int rw = wm + mi * 16 + (lane & 15);
                uint32_t off = rw * 64 + ((lc ^ ((rw >> 1) & 3)) << 4);
                ldsm4(ah[mi], b + off);
                ldsm4(al[mi], b + TILE_BYTES + off);
            }
            uint32_t bh[4][2], bl[4][2];
            #pragma unroll
            for (int bi = 0; bi < 2; bi++) {
                int rw = wn + bi * 16 + (lane & 15);
                uint32_t off = rw * 64 + ((lc ^ ((rw >> 1) & 3)) << 4);
                uint32_t t[4];
                ldsm4(t, b + 2 * TILE_BYTES + off);
                bh[2*bi][0] = t[0]; bh[2*bi][1] = t[2];
                bh[2*bi+1][0] = t[1]; bh[2*bi+1][1] = t[3];
                ldsm4(t, b + 3 * TILE_BYTES + off);
                bl[2*bi][0] = t[0]; bl[2*bi][1] = t[2];
                bl[2*bi+1][0] = t[1]; bl[2*bi+1][1] = t[3];
            }
            #pragma unroll
            for (int mi = 0; mi < 4; mi++)
                #pragma unroll
                for (int ni = 0; ni < 4; ni++) {
                    mma_bf16(acc[mi][ni], ah[mi], bh[ni]);
                    mma_bf16(acc[mi][ni], ah[mi], bl[ni]);
                    mma_bf16(acc[mi][ni], al[mi], bh[ni]);
                }
        }
    };

    const int NC = (RK_ / KSPLIT) / 32;   // 48
    fill(0, 0); CP_COMMIT();
    fill(1, 1); CP_COMMIT();
    #pragma unroll 1
    for (int c = 0; c < NC; c++) {
        CP_WAIT1();
        __syncthreads();
        if (c + 2 < NC) { fill(c + 2, (c + 2) % NSTG); CP_COMMIT(); }
        compute(c % NSTG);
    }

    // epilogue: fp32 partials
    int mrow = lane >> 2, kcol = (lane & 3) * 2;
    #pragma unroll
    for (int mi = 0; mi < 4; mi++)
        #pragma unroll
        for (int ni = 0; ni < 4; ni++) {
            int dg = d0 + wn + ni * 8 + kcol;
            int m0 = n0 + wm + mi * 16 + mrow;
            #pragma unroll
            for (int half = 0; half < 2; half++) {
                float2 v = make_float2(acc[mi][ni][half * 2 + 0],
                                       acc[mi][ni][half * 2 + 1]);
                *(float2*)(g_part + ((size_t)ks * N_ + m0 + half * 8) * D_ + dg) = v;
            }
        }
}

// out += sum of KSPLIT partials
__global__ void reduce_out(float* __restrict__ out) {
    size_t i = ((size_t)blockIdx.x * blockDim.x + threadIdx.x) * 4;
    float4 o = *(float4*)(out + i);
    #pragma unroll
    for (int s = 0; s < KSPLIT; s++) {
        float4 p = *(const float4*)(g_part + (size_t)s * N_ * D_ + i);
        o.x += p.x; o.y += p.y; o.z += p.z; o.w += p.w;
    }
    *(float4*)(out + i) = o;
}

// ---------------------------------------------------------------------------
// Launch
// ---------------------------------------------------------------------------
extern "C" void kernel_launch(void* const* d_in, const int* in_sizes, int n_in,
                              void* d_out, int out_size) {
    const float* x       = (const float*)d_in[0];
    const float* lambdas = (const float*)d_in[1];
    const float* bases   = (const float*)d_in[2];
    const float* invb    = (const float*)d_in[3];
    const float* means   = (const float*)d_in[4];
    const int*   resid   = (const int*)d_in[5];
    const int*   abl     = (const int*)d_in[6];
    const int*   lengths = (const int*)d_in[7];
    float*       out     = (float*)d_out;

    int total_lam = in_sizes[1];

    cudaFuncSetAttribute(gemm1_mma, cudaFuncAttributeMaxDynamicSharedMemorySize, SMEM_TOTAL);
    cudaFuncSetAttribute(gemm2_mma, cudaFuncAttributeMaxDynamicSharedMemorySize, SMEM_TOTAL);

    prep_kernel<<<R_, 128>>>(lambdas, bases, means, lengths, total_lam);
    convert_blam<<<(R_ * K_ * D_ / 4) / 256, 256>>>(bases);
    convert_ibt<<<dim3(RK_ / 32, D_ / 32), dim3(32, 8)>>>(invb);
    abl_kernel<<<(N_ * D_) / 256, 256>>>(x, abl, out);
    gemm1_mma<<<dim3(N_ / 128, R_), 256, SMEM_TOTAL>>>(x, resid);
    gemm2_mma<<<dim3(N_ / 128, D_ / 128, KSPLIT), 256, SMEM_TOTAL>>>();
    reduce_out<<<(N_ * D_ / 4) / 256, 256>>>(out);
}

// round 9
// speedup vs baseline: 4.8146x; 1.0404x over previous
#include <cuda_runtime.h>
#include <cuda_bf16.h>
#include <cstdint>

#define N_   1024
#define S_   144
#define R_   96
#define K_   128
#define D_   768
#define ABL_ 48
#define RK_  (R_ * K_)   // 12288
#define KSPLIT 6

// ---------------------------------------------------------------------------
// Device-global scratch (no allocation allowed in kernel_launch)
// ---------------------------------------------------------------------------
__device__ float g_lam[RK_];
__device__ float g_c0[RK_];
__device__ __align__(16) __nv_bfloat16 g_blh[(size_t)R_ * K_ * D_];  // bases*lam hi [rk][d]
__device__ __align__(16) __nv_bfloat16 g_bll[(size_t)R_ * K_ * D_];
__device__ __align__(16) __nv_bfloat16 g_chi[(size_t)N_ * RK_];      // coeffs hi [n][rk]
__device__ __align__(16) __nv_bfloat16 g_clo[(size_t)N_ * RK_];
__device__ __align__(16) __nv_bfloat16 g_ibth[(size_t)D_ * RK_];     // invb^T hi [d][j]
__device__ __align__(16) __nv_bfloat16 g_ibtl[(size_t)D_ * RK_];
__device__ float g_part[(size_t)KSPLIT * N_ * D_];

// ---------------------------------------------------------------------------
// Helpers (base-ISA only: cp.async / ldmatrix / mma.sync — no tcgen05)
// ---------------------------------------------------------------------------
__device__ __forceinline__ uint32_t smem_u32(const void* p) {
    uint32_t a;
    asm("{ .reg .u64 t; cvta.to.shared.u64 t, %1; cvt.u32.u64 %0, t; }"
        : "=r"(a) : "l"(p));
    return a;
}

__device__ __forceinline__ void cp16(uint32_t dst, const void* src) {
    asm volatile("cp.async.cg.shared.global [%0], [%1], 16;" :: "r"(dst), "l"(src));
}
#define CP_COMMIT() asm volatile("cp.async.commit_group;" ::: "memory")
#define CP_WAIT1()  asm volatile("cp.async.wait_group 1;"  ::: "memory")

__device__ __forceinline__ void ldsm4(uint32_t* r, uint32_t a) {
    asm volatile("ldmatrix.sync.aligned.m8n8.x4.shared.b16 {%0,%1,%2,%3}, [%4];"
        : "=r"(r[0]), "=r"(r[1]), "=r"(r[2]), "=r"(r[3]) : "r"(a));
}

__device__ __forceinline__ void mma_bf16(float* d, const uint32_t* a, const uint32_t* b) {
    asm volatile(
        "mma.sync.aligned.m16n8k16.row.col.f32.bf16.bf16.f32 "
        "{%0,%1,%2,%3}, {%4,%5,%6,%7}, {%8,%9}, {%0,%1,%2,%3};"
        : "+f"(d[0]), "+f"(d[1]), "+f"(d[2]), "+f"(d[3])
        : "r"(a[0]), "r"(a[1]), "r"(a[2]), "r"(a[3]), "r"(b[0]), "r"(b[1]));
}

__device__ __forceinline__ void split1(float v, __nv_bfloat16& h, __nv_bfloat16& l) {
    h = __float2bfloat16(v);
    l = __float2bfloat16(v - __bfloat162float(h));
}
__device__ __forceinline__ uint32_t pack2(__nv_bfloat16 a, __nv_bfloat16 b) {
    uint16_t x = *(uint16_t*)&a, y = *(uint16_t*)&b;
    return (uint32_t)x | ((uint32_t)y << 16);
}

// smem tiles: rows of 32 bf16 (64B), 16B-chunk swizzle: phys = ch ^ ((row>>1)&3)
// GEMM1: 128x128 tile, stage = Ah|Al|Bh|Bl of 8KB each
#define TILE_BYTES 8192
#define STG_BYTES  32768
#define NSTG 3
#define SMEM_G1 (NSTG * STG_BYTES)
// GEMM2: 256(n) x 128(d) tile, stage = Ah|Al (16KB each) | Bh|Bl (8KB each)
#define A2_T 16384
#define B2_T 8192
#define STG2_BYTES (2 * A2_T + 2 * B2_T)   // 49152
#define SMEM_G2 (NSTG * STG2_BYTES)        // 147456

// ---------------------------------------------------------------------------
// Small kernels
// ---------------------------------------------------------------------------
__global__ void prep_kernel(const float* __restrict__ lambdas,
                            const float* __restrict__ bases,
                            const float* __restrict__ means,
                            const int*   __restrict__ lengths,
                            int total_lam) {
    int r = blockIdx.x;
    int k = threadIdx.x;

    __shared__ float smean[D_];
    for (int d = threadIdx.x; d < D_; d += blockDim.x)
        smean[d] = means[r * D_ + d];
    __syncthreads();

    int off = 0;
    for (int i = 0; i < r; i++) off += lengths[i];
    int len = lengths[r];

    float lam = 0.0f;
    if (k < len) {
        int idx = off + k;
        if (idx > total_lam - 1) idx = total_lam - 1;
        lam = lambdas[idx];
    }

    const float* brow = bases + ((size_t)r * K_ + k) * D_;
    float dot = 0.0f;
    #pragma unroll 8
    for (int d = 0; d < D_; d++) dot += smean[d] * brow[d];

    g_lam[r * K_ + k] = lam;
    g_c0[r * K_ + k]  = lam * dot;
}

// bases*lam -> bf16 hi/lo
__global__ void convert_blam(const float* __restrict__ bases) {
    size_t i = ((size_t)blockIdx.x * blockDim.x + threadIdx.x) * 4;
    int rk = (int)(i / D_);
    float lam = g_lam[rk];
    float4 v = *(const float4*)(bases + i);
    __align__(8) __nv_bfloat16 h[4], l[4];
    split1(v.x * lam, h[0], l[0]); split1(v.y * lam, h[1], l[1]);
    split1(v.z * lam, h[2], l[2]); split1(v.w * lam, h[3], l[3]);
    *(uint2*)(g_blh + i) = *(uint2*)h;
    *(uint2*)(g_bll + i) = *(uint2*)l;
}

// invb [j][d] -> transposed bf16 hi/lo [d][j]
__global__ void convert_ibt(const float* __restrict__ invb) {
    __shared__ float t[32][33];
    int jb = blockIdx.x * 32, db = blockIdx.y * 32;
    int tx = threadIdx.x, ty = threadIdx.y;  // 32 x 8
    #pragma unroll
    for (int k = 0; k < 4; k++)
        t[ty + 8 * k][tx] = invb[(size_t)(jb + ty + 8 * k) * D_ + db + tx];
    __syncthreads();
    #pragma unroll
    for (int k = 0; k < 4; k++) {
        float v = t[tx][ty + 8 * k];
        __nv_bfloat16 h, l;
        split1(v, h, l);
        size_t o = (size_t)(db + ty + 8 * k) * RK_ + jb + tx;
        g_ibth[o] = h;
        g_ibtl[o] = l;
    }
}

// ablated-slice sum (float4 vectorized)
__global__ void abl_kernel(const float* __restrict__ x,
                           const int* __restrict__ abl,
                           float* __restrict__ out) {
    __shared__ int sabl[ABL_];
    if (threadIdx.x < ABL_) sabl[threadIdx.x] = abl[threadIdx.x];
    __syncthreads();

    size_t i4 = ((size_t)blockIdx.x * blockDim.x + threadIdx.x) * 4;
    int n = (int)(i4 / D_);
    int d = (int)(i4 - (size_t)n * D_);
    const float* xp = x + (size_t)n * S_ * D_ + d;

    float4 s = make_float4(0.f, 0.f, 0.f, 0.f);
    #pragma unroll
    for (int a = 0; a < ABL_; a++) {
        float4 v = __ldg((const float4*)(xp + (size_t)sabl[a] * D_));
        s.x += v.x; s.y += v.y; s.z += v.z; s.w += v.w;
    }
    *(float4*)(out + i4) = s;
}

// ---------------------------------------------------------------------------
// GEMM1 (mma.sync bf16x3, fused x gather+split in fill):
//   coeffs[n, r*K+k] = x[n, s_r, :] . blam[r,k,:] - c0[r,k]
// Block 128(m=n) x 128(n=k) x BK=32(d). grid=(8, 96), 256 thr, 8 warps 2x4.
// ---------------------------------------------------------------------------
#define G1_NC 24

__global__ __launch_bounds__(256)
void gemm1_mma(const float* __restrict__ x, const int* __restrict__ resid) {
    extern __shared__ __align__(128) char sm[];
    uint32_t sbase = smem_u32(sm);
    int tid = threadIdx.x, lane = tid & 31, wid = tid >> 5;
    int r = blockIdx.y, n0 = blockIdx.x * 128;
    int s = __ldg(resid + r);
    int wm = (wid >> 2) * 64, wn = (wid & 3) * 32;

    const float* Ax = x + ((size_t)n0 * S_ + s) * D_;
    const __nv_bfloat16* Bh = g_blh + (size_t)r * K_ * D_;
    const __nv_bfloat16* Bl = g_bll + (size_t)r * K_ * D_;

    float acc[4][4][4];
    #pragma unroll
    for (int a = 0; a < 4; a++)
        #pragma unroll
        for (int b = 0; b < 4; b++)
            #pragma unroll
            for (int c = 0; c < 4; c++) acc[a][b][c] = 0.0f;

    int frow = tid >> 2, fch = tid & 3;
    float4 ra[4];

    auto ldgA = [&](int c) {
        int d0 = c * 32;
        #pragma unroll
        for (int i = 0; i < 2; i++) {
            int rw = frow + 64 * i;
            const float* p = Ax + (size_t)rw * (S_ * D_) + d0 + fch * 8;
            ra[2 * i]     = __ldg((const float4*)p);
            ra[2 * i + 1] = __ldg((const float4*)(p + 4));
        }
    };

    auto stsA = [&](int stg) {
        char* b = sm + stg * STG_BYTES;
        #pragma unroll
        for (int i = 0; i < 2; i++) {
            int rw = frow + 64 * i;
            uint32_t off = rw * 64 + ((fch ^ ((rw >> 1) & 3)) << 4);
            float vv[8] = {ra[2*i].x, ra[2*i].y, ra[2*i].z, ra[2*i].w,
                           ra[2*i+1].x, ra[2*i+1].y, ra[2*i+1].z, ra[2*i+1].w};
            __align__(16) __nv_bfloat16 h[8], l[8];
            #pragma unroll
            for (int j = 0; j < 8; j++) split1(vv[j], h[j], l[j]);
            *(uint4*)(b + off)              = *(uint4*)h;
            *(uint4*)(b + TILE_BYTES + off) = *(uint4*)l;
        }
    };

    auto cpB = [&](int c, int stg) {
        uint32_t b = sbase + stg * STG_BYTES;
        int d0 = c * 32;
        #pragma unroll
        for (int i = 0; i < 2; i++) {
            int rw = frow + 64 * i;
            uint32_t off = rw * 64 + ((fch ^ ((rw >> 1) & 3)) << 4);
            size_t so = (size_t)rw * D_ + d0 + fch * 8;
            cp16(b + 2 * TILE_BYTES + off, Bh + so);
            cp16(b + 3 * TILE_BYTES + off, Bl + so);
        }
    };

    auto compute = [&](int stg) {
        uint32_t b = sbase + stg * STG_BYTES;
        #pragma unroll
        for (int kk = 0; kk < 2; kk++) {
            int lc = kk * 2 + (lane >> 4);
            uint32_t ah[4][4], al[4][4];
            #pragma unroll
            for (int mi = 0; mi < 4; mi++) {
                int rw = wm + mi * 16 + (lane & 15);
                uint32_t off = rw * 64 + ((lc ^ ((rw >> 1) & 3)) << 4);
                ldsm4(ah[mi], b + off);
                ldsm4(al[mi], b + TILE_BYTES + off);
            }
            uint32_t bh[4][2], bl[4][2];
            #pragma unroll
            for (int bi = 0; bi < 2; bi++) {
                int rw = wn + bi * 16 + (lane & 15);
                uint32_t off = rw * 64 + ((lc ^ ((rw >> 1) & 3)) << 4);
                uint32_t t[4];
                ldsm4(t, b + 2 * TILE_BYTES + off);
                bh[2*bi][0] = t[0]; bh[2*bi][1] = t[2];
                bh[2*bi+1][0] = t[1]; bh[2*bi+1][1] = t[3];
                ldsm4(t, b + 3 * TILE_BYTES + off);
                bl[2*bi][0] = t[0]; bl[2*bi][1] = t[2];
                bl[2*bi+1][0] = t[1]; bl[2*bi+1][1] = t[3];
            }
            #pragma unroll
            for (int mi = 0; mi < 4; mi++)
                #pragma unroll
                for (int ni = 0; ni < 4; ni++) {
                    mma_bf16(acc[mi][ni], ah[mi], bh[ni]);
                    mma_bf16(acc[mi][ni], ah[mi], bl[ni]);
                    mma_bf16(acc[mi][ni], al[mi], bh[ni]);
                }
        }
    };

    ldgA(0); stsA(0); cpB(0, 0); CP_COMMIT();
    ldgA(1); stsA(1); cpB(1, 1); CP_COMMIT();
    ldgA(2);

    #pragma unroll 1
    for (int c = 0; c < G1_NC; c++) {
        CP_WAIT1();
        __syncthreads();
        if (c + 2 < G1_NC) {
            int stg = (c + 2) % NSTG;
            stsA(stg);
            cpB(c + 2, stg); CP_COMMIT();
            if (c + 3 < G1_NC) ldgA(c + 3);
        }
        compute(c % NSTG);
    }

    int mrow = lane >> 2, kcol = (lane & 3) * 2;
    #pragma unroll
    for (int mi = 0; mi < 4; mi++)
        #pragma unroll
        for (int ni = 0; ni < 4; ni++) {
            int kg = wn + ni * 8 + kcol;
            float c00 = g_c0[r * K_ + kg], c01 = g_c0[r * K_ + kg + 1];
            int m0 = n0 + wm + mi * 16 + mrow;
            #pragma unroll
            for (int half = 0; half < 2; half++) {
                float v0 = acc[mi][ni][half * 2 + 0] - c00;
                float v1 = acc[mi][ni][half * 2 + 1] - c01;
                __nv_bfloat16 h0, l0, h1, l1;
                split1(v0, h0, l0);
                split1(v1, h1, l1);
                size_t o = (size_t)(m0 + half * 8) * RK_ + r * K_ + kg;
                *(uint32_t*)(g_chi + o) = pack2(h0, h1);
                *(uint32_t*)(g_clo + o) = pack2(l0, l1);
            }
        }
}

// ---------------------------------------------------------------------------
// GEMM2 (mma.sync bf16x3): part[ks][n][d] = sum_j coeffs[n,j] * invbT[d,j]
// Block 256(n) x 128(d) x BK=32(j), split-K=6 (2048 j per split).
// grid=(4, 6, 6) = 144 CTAs = one full wave. 512 thr, 16 warps 4x4, 64x32/warp.
// ---------------------------------------------------------------------------
__global__ __launch_bounds__(512)
void gemm2_mma() {
    extern __shared__ __align__(128) char sm[];
    uint32_t sbase = smem_u32(sm);
    int tid = threadIdx.x, lane = tid & 31, wid = tid >> 5;
    int n0 = blockIdx.x * 256, d0 = blockIdx.y * 128, ks = blockIdx.z;
    int jbase = ks * (RK_ / KSPLIT);   // 2048 per split
    int wm = (wid >> 2) * 64, wn = (wid & 3) * 32;

    const __nv_bfloat16* Ah = g_chi  + (size_t)n0 * RK_ + jbase;
    const __nv_bfloat16* Al = g_clo  + (size_t)n0 * RK_ + jbase;
    const __nv_bfloat16* Bh = g_ibth + (size_t)d0 * RK_ + jbase;
    const __nv_bfloat16* Bl = g_ibtl + (size_t)d0 * RK_ + jbase;

    float acc[4][4][4];
    #pragma unroll
    for (int a = 0; a < 4; a++)
        #pragma unroll
        for (int b = 0; b < 4; b++)
            #pragma unroll
            for (int c = 0; c < 4; c++) acc[a][b][c] = 0.0f;

    int frow = tid >> 2, fch = tid & 3;   // frow 0..127, 4 chunks/row

    auto fill = [&](int c, int stg) {
        uint32_t b = sbase + stg * STG2_BYTES;
        int j0 = c * 32;
        // A: 256 rows (hi + lo)
        #pragma unroll
        for (int i = 0; i < 2; i++) {
            int rw = frow + 128 * i;
            uint32_t off = rw * 64 + ((fch ^ ((rw >> 1) & 3)) << 4);
            size_t so = (size_t)rw * RK_ + j0 + fch * 8;
            cp16(b +        off, Ah + so);
            cp16(b + A2_T + off, Al + so);
        }
        // B: 128 rows (hi + lo)
        {
            int rw = frow;
            uint32_t off = rw * 64 + ((fch ^ ((rw >> 1) & 3)) << 4);
            size_t so = (size_t)rw * RK_ + j0 + fch * 8;
            cp16(b + 2 * A2_T +        off, Bh + so);
            cp16(b + 2 * A2_T + B2_T + off, Bl + so);
        }
    };

    auto compute = [&](int stg) {
        uint32_t b = sbase + stg * STG2_BYTES;
        #pragma unroll
        for (int kk = 0; kk < 2; kk++) {
            int lc = kk * 2 + (lane >> 4);
            uint32_t ah[4][4], al[4][4];
            #pragma unroll
            for (int mi = 0; mi < 4; mi++) {
                int rw = wm + mi * 16 + (lane & 15);
                uint32_t off = rw * 64 + ((lc ^ ((rw >> 1) & 3)) << 4);
                ldsm4(ah[mi], b + off);
                ldsm4(al[mi], b + A2_T + off);
            }
            uint32_t bh[4][2], bl[4][2];
            #pragma unroll
            for (int bi = 0; bi < 2; bi++) {
                int rw = wn + bi * 16 + (lane & 15);
                uint32_t off = rw * 64 + ((lc ^ ((rw >> 1) & 3)) << 4);
                uint32_t t[4];
                ldsm4(t, b + 2 * A2_T + off);
                bh[2*bi][0] = t[0]; bh[2*bi][1] = t[2];
                bh[2*bi+1][0] = t[1]; bh[2*bi+1][1] = t[3];
                ldsm4(t, b + 2 * A2_T + B2_T + off);
                bl[2*bi][0] = t[0]; bl[2*bi][1] = t[2];
                bl[2*bi+1][0] = t[1]; bl[2*bi+1][1] = t[3];
            }
            #pragma unroll
            for (int mi = 0; mi < 4; mi++)
                #pragma unroll
                for (int ni = 0; ni < 4; ni++) {
                    mma_bf16(acc[mi][ni], ah[mi], bh[ni]);
                    mma_bf16(acc[mi][ni], ah[mi], bl[ni]);
                    mma_bf16(acc[mi][ni], al[mi], bh[ni]);
                }
        }
    };

    const int NC = (RK_ / KSPLIT) / 32;   // 64
    fill(0, 0); CP_COMMIT();
    fill(1, 1); CP_COMMIT();
    #pragma unroll 1
    for (int c = 0; c < NC; c++) {
        CP_WAIT1();
        __syncthreads();
        if (c + 2 < NC) { fill(c + 2, (c + 2) % NSTG); CP_COMMIT(); }
        compute(c % NSTG);
    }

    // epilogue: fp32 partials
    int mrow = lane >> 2, kcol = (lane & 3) * 2;
    #pragma unroll
    for (int mi = 0; mi < 4; mi++)
        #pragma unroll
        for (int ni = 0; ni < 4; ni++) {
            int dg = d0 + wn + ni * 8 + kcol;
            int m0 = n0 + wm + mi * 16 + mrow;
            #pragma unroll
            for (int half = 0; half < 2; half++) {
                float2 v = make_float2(acc[mi][ni][half * 2 + 0],
                                       acc[mi][ni][half * 2 + 1]);
                *(float2*)(g_part + ((size_t)ks * N_ + m0 + half * 8) * D_ + dg) = v;
            }
        }
}

// out += sum of KSPLIT partials
__global__ void reduce_out(float* __restrict__ out) {
    size_t i = ((size_t)blockIdx.x * blockDim.x + threadIdx.x) * 4;
    float4 o = *(float4*)(out + i);
    #pragma unroll
    for (int s = 0; s < KSPLIT; s++) {
        float4 p = *(const float4*)(g_part + (size_t)s * N_ * D_ + i);
        o.x += p.x; o.y += p.y; o.z += p.z; o.w += p.w;
    }
    *(float4*)(out + i) = o;
}

// ---------------------------------------------------------------------------
// Launch
// ---------------------------------------------------------------------------
extern "C" void kernel_launch(void* const* d_in, const int* in_sizes, int n_in,
                              void* d_out, int out_size) {
    const float* x       = (const float*)d_in[0];
    const float* lambdas = (const float*)d_in[1];
    const float* bases   = (const float*)d_in[2];
    const float* invb    = (const float*)d_in[3];
    const float* means   = (const float*)d_in[4];
    const int*   resid   = (const int*)d_in[5];
    const int*   abl     = (const int*)d_in[6];
    const int*   lengths = (const int*)d_in[7];
    float*       out     = (float*)d_out;

    int total_lam = in_sizes[1];

    cudaFuncSetAttribute(gemm1_mma, cudaFuncAttributeMaxDynamicSharedMemorySize, SMEM_G1);
    cudaFuncSetAttribute(gemm2_mma, cudaFuncAttributeMaxDynamicSharedMemorySize, SMEM_G2);

    prep_kernel<<<R_, 128>>>(lambdas, bases, means, lengths, total_lam);
    convert_blam<<<(R_ * K_ * D_ / 4) / 256, 256>>>(bases);
    convert_ibt<<<dim3(RK_ / 32, D_ / 32), dim3(32, 8)>>>(invb);
    abl_kernel<<<(N_ * D_ / 4) / 256, 256>>>(x, abl, out);
    gemm1_mma<<<dim3(N_ / 128, R_), 256, SMEM_G1>>>(x, resid);
    gemm2_mma<<<dim3(N_ / 256, D_ / 128, KSPLIT), 512, SMEM_G2>>>();
    reduce_out<<<(N_ * D_ / 4) / 256, 256>>>(out);
}

// round 10
// speedup vs baseline: 4.8826x; 1.0141x over previous
#include <cuda_runtime.h>
#include <cuda_bf16.h>
#include <cstdint>

#define N_   1024
#define S_   144
#define R_   96
#define K_   128
#define D_   768
#define ABL_ 48
#define RK_  (R_ * K_)   // 12288
#define KSPLIT 6

// ---------------------------------------------------------------------------
// Device-global scratch (no allocation allowed in kernel_launch)
// ---------------------------------------------------------------------------
__device__ float g_c0[RK_];
__device__ __align__(16) __nv_bfloat16 g_blh[(size_t)R_ * K_ * D_];  // bases*lam hi [rk][d]
__device__ __align__(16) __nv_bfloat16 g_bll[(size_t)R_ * K_ * D_];
__device__ __align__(16) __nv_bfloat16 g_chi[(size_t)N_ * RK_];      // coeffs hi [n][rk]
__device__ __align__(16) __nv_bfloat16 g_clo[(size_t)N_ * RK_];
__device__ __align__(16) __nv_bfloat16 g_ibth[(size_t)D_ * RK_];     // invb^T hi [d][j]
__device__ __align__(16) __nv_bfloat16 g_ibtl[(size_t)D_ * RK_];
__device__ float g_part[(size_t)KSPLIT * N_ * D_];

// ---------------------------------------------------------------------------
// Helpers (base-ISA only: cp.async / ldmatrix / mma.sync — no tcgen05)
// ---------------------------------------------------------------------------
__device__ __forceinline__ uint32_t smem_u32(const void* p) {
    uint32_t a;
    asm("{ .reg .u64 t; cvta.to.shared.u64 t, %1; cvt.u32.u64 %0, t; }"
        : "=r"(a) : "l"(p));
    return a;
}

__device__ __forceinline__ void cp16(uint32_t dst, const void* src) {
    asm volatile("cp.async.cg.shared.global [%0], [%1], 16;" :: "r"(dst), "l"(src));
}
#define CP_COMMIT() asm volatile("cp.async.commit_group;" ::: "memory")
#define CP_WAIT1()  asm volatile("cp.async.wait_group 1;"  ::: "memory")
#define CP_WAIT0()  asm volatile("cp.async.wait_group 0;"  ::: "memory")

__device__ __forceinline__ void ldsm4(uint32_t* r, uint32_t a) {
    asm volatile("ldmatrix.sync.aligned.m8n8.x4.shared.b16 {%0,%1,%2,%3}, [%4];"
        : "=r"(r[0]), "=r"(r[1]), "=r"(r[2]), "=r"(r[3]) : "r"(a));
}

__device__ __forceinline__ void mma_bf16(float* d, const uint32_t* a, const uint32_t* b) {
    asm volatile(
        "mma.sync.aligned.m16n8k16.row.col.f32.bf16.bf16.f32 "
        "{%0,%1,%2,%3}, {%4,%5,%6,%7}, {%8,%9}, {%0,%1,%2,%3};"
        : "+f"(d[0]), "+f"(d[1]), "+f"(d[2]), "+f"(d[3])
        : "r"(a[0]), "r"(a[1]), "r"(a[2]), "r"(a[3]), "r"(b[0]), "r"(b[1]));
}

__device__ __forceinline__ void split1(float v, __nv_bfloat16& h, __nv_bfloat16& l) {
    h = __float2bfloat16(v);
    l = __float2bfloat16(v - __bfloat162float(h));
}
__device__ __forceinline__ uint32_t pack2(__nv_bfloat16 a, __nv_bfloat16 b) {
    uint16_t x = *(uint16_t*)&a, y = *(uint16_t*)&b;
    return (uint32_t)x | ((uint32_t)y << 16);
}

// smem tiles: rows of 32 bf16 (64B), 16B-chunk swizzle: phys = ch ^ ((row>>1)&3)
// GEMM1: 128x128 tile, stage = Ah|Al|Bh|Bl of 8KB each, 2 stages -> 64KB, 2 CTAs/SM
#define TILE_BYTES 8192
#define STG_BYTES  32768
#define NSTG1 2
#define SMEM_G1 (NSTG1 * STG_BYTES)
// GEMM2: 256(n) x 128(d) tile, stage = Ah|Al (16KB each) | Bh|Bl (8KB each), 3 stages
#define A2_T 16384
#define B2_T 8192
#define STG2_BYTES (2 * A2_T + 2 * B2_T)   // 49152
#define NSTG2 3
#define SMEM_G2 (NSTG2 * STG2_BYTES)       // 147456

// ---------------------------------------------------------------------------
// prep + blam convert fused: lam, c0, and bases*lam bf16 hi/lo per r
// grid = R_, 256 threads
// ---------------------------------------------------------------------------
__global__ void prep_blam(const float* __restrict__ lambdas,
                          const float* __restrict__ bases,
                          const float* __restrict__ means,
                          const int*   __restrict__ lengths,
                          int total_lam) {
    int r = blockIdx.x, tid = threadIdx.x;

    __shared__ float smean[D_];
    __shared__ float slam[K_];
    __shared__ float sdot[256];

    for (int d = tid; d < D_; d += 256)
        smean[d] = means[r * D_ + d];
    __syncthreads();

    int off = 0;
    for (int i = 0; i < r; i++) off += lengths[i];
    int len = lengths[r];

    // 2 threads per k: halves of the D-dot
    int k = tid >> 1, h = tid & 1;
    const float* brow = bases + ((size_t)r * K_ + k) * D_;
    float dot = 0.0f;
    #pragma unroll 8
    for (int d = h * (D_ / 2); d < (h + 1) * (D_ / 2); d++)
        dot += smean[d] * brow[d];
    sdot[tid] = dot;
    __syncthreads();

    if (h == 0) {
        float lam = 0.0f;
        if (k < len) {
            int idx = off + k;
            if (idx > total_lam - 1) idx = total_lam - 1;
            lam = lambdas[idx];
        }
        g_c0[r * K_ + k] = lam * (sdot[tid] + sdot[tid + 1]);
        slam[k] = lam;
    }
    __syncthreads();

    // write blam hi/lo (bases rows hot in L1/L2 from the dot pass)
    const float* bbase = bases + (size_t)r * K_ * D_;
    for (int i4 = tid * 4; i4 < K_ * D_; i4 += 256 * 4) {
        float lam = slam[i4 / D_];
        float4 v = *(const float4*)(bbase + i4);
        __align__(8) __nv_bfloat16 hh[4], ll[4];
        split1(v.x * lam, hh[0], ll[0]); split1(v.y * lam, hh[1], ll[1]);
        split1(v.z * lam, hh[2], ll[2]); split1(v.w * lam, hh[3], ll[3]);
        size_t o = (size_t)r * K_ * D_ + i4;
        *(uint2*)(g_blh + o) = *(uint2*)hh;
        *(uint2*)(g_bll + o) = *(uint2*)ll;
    }
}

// invb [j][d] -> transposed bf16 hi/lo [d][j]
__global__ void convert_ibt(const float* __restrict__ invb) {
    __shared__ float t[32][33];
    int jb = blockIdx.x * 32, db = blockIdx.y * 32;
    int tx = threadIdx.x, ty = threadIdx.y;  // 32 x 8
    #pragma unroll
    for (int k = 0; k < 4; k++)
        t[ty + 8 * k][tx] = invb[(size_t)(jb + ty + 8 * k) * D_ + db + tx];
    __syncthreads();
    #pragma unroll
    for (int k = 0; k < 4; k++) {
        float v = t[tx][ty + 8 * k];
        __nv_bfloat16 h, l;
        split1(v, h, l);
        size_t o = (size_t)(db + ty + 8 * k) * RK_ + jb + tx;
        g_ibth[o] = h;
        g_ibtl[o] = l;
    }
}

// ---------------------------------------------------------------------------
// GEMM1 (mma.sync bf16x3, fused x gather+split, 2-stage, 2 CTAs/SM):
//   coeffs[n, r*K+k] = x[n, s_r, :] . blam[r,k,:] - c0[r,k]
// Block 128(m=n) x 128(n=k) x BK=32(d). grid=(8, 96), 256 thr, 8 warps 2x4.
// ---------------------------------------------------------------------------
#define G1_NC 24

__global__ __launch_bounds__(256, 2)
void gemm1_mma(const float* __restrict__ x, const int* __restrict__ resid) {
    extern __shared__ __align__(128) char sm[];
    uint32_t sbase = smem_u32(sm);
    int tid = threadIdx.x, lane = tid & 31, wid = tid >> 5;
    int r = blockIdx.y, n0 = blockIdx.x * 128;
    int s = __ldg(resid + r);
    int wm = (wid >> 2) * 64, wn = (wid & 3) * 32;

    const float* Ax = x + ((size_t)n0 * S_ + s) * D_;
    const __nv_bfloat16* Bh = g_blh + (size_t)r * K_ * D_;
    const __nv_bfloat16* Bl = g_bll + (size_t)r * K_ * D_;

    float acc[4][4][4];
    #pragma unroll
    for (int a = 0; a < 4; a++)
        #pragma unroll
        for (int b = 0; b < 4; b++)
            #pragma unroll
            for (int c = 0; c < 4; c++) acc[a][b][c] = 0.0f;

    int frow = tid >> 2, fch = tid & 3;
    float4 ra[4];

    auto ldgA = [&](int c) {
        int d0 = c * 32;
        #pragma unroll
        for (int i = 0; i < 2; i++) {
            int rw = frow + 64 * i;
            const float* p = Ax + (size_t)rw * (S_ * D_) + d0 + fch * 8;
            ra[2 * i]     = __ldg((const float4*)p);
            ra[2 * i + 1] = __ldg((const float4*)(p + 4));
        }
    };

    auto stsA = [&](int stg) {
        char* b = sm + stg * STG_BYTES;
        #pragma unroll
        for (int i = 0; i < 2; i++) {
            int rw = frow + 64 * i;
            uint32_t off = rw * 64 + ((fch ^ ((rw >> 1) & 3)) << 4);
            float vv[8] = {ra[2*i].x, ra[2*i].y, ra[2*i].z, ra[2*i].w,
                           ra[2*i+1].x, ra[2*i+1].y, ra[2*i+1].z, ra[2*i+1].w};
            __align__(16) __nv_bfloat16 h[8], l[8];
            #pragma unroll
            for (int j = 0; j < 8; j++) split1(vv[j], h[j], l[j]);
            *(uint4*)(b + off)              = *(uint4*)h;
            *(uint4*)(b + TILE_BYTES + off) = *(uint4*)l;
        }
    };

    auto cpB = [&](int c, int stg) {
        uint32_t b = sbase + stg * STG_BYTES;
        int d0 = c * 32;
        #pragma unroll
        for (int i = 0; i < 2; i++) {
            int rw = frow + 64 * i;
            uint32_t off = rw * 64 + ((fch ^ ((rw >> 1) & 3)) << 4);
            size_t so = (size_t)rw * D_ + d0 + fch * 8;
            cp16(b + 2 * TILE_BYTES + off, Bh + so);
            cp16(b + 3 * TILE_BYTES + off, Bl + so);
        }
    };

    auto compute = [&](int stg) {
        uint32_t b = sbase + stg * STG_BYTES;
        #pragma unroll
        for (int kk = 0; kk < 2; kk++) {
            int lc = kk * 2 + (lane >> 4);
            uint32_t bh[4][2], bl[4][2];
            #pragma unroll
            for (int bi = 0; bi < 2; bi++) {
                int rw = wn + bi * 16 + (lane & 15);
                uint32_t off = rw * 64 + ((lc ^ ((rw >> 1) & 3)) << 4);
                uint32_t t[4];
                ldsm4(t, b + 2 * TILE_BYTES + off);
                bh[2*bi][0] = t[0]; bh[2*bi][1] = t[2];
                bh[2*bi+1][0] = t[1]; bh[2*bi+1][1] = t[3];
                ldsm4(t, b + 3 * TILE_BYTES + off);
                bl[2*bi][0] = t[0]; bl[2*bi][1] = t[2];
                bl[2*bi+1][0] = t[1]; bl[2*bi+1][1] = t[3];
            }
            #pragma unroll
            for (int mi = 0; mi < 4; mi++) {
                int rw = wm + mi * 16 + (lane & 15);
                uint32_t off = rw * 64 + ((lc ^ ((rw >> 1) & 3)) << 4);
                uint32_t ah[4], al[4];
                ldsm4(ah, b + off);
                ldsm4(al, b + TILE_BYTES + off);
                #pragma unroll
                for (int ni = 0; ni < 4; ni++) {
                    mma_bf16(acc[mi][ni], ah, bh[ni]);
                    mma_bf16(acc[mi][ni], ah, bl[ni]);
                    mma_bf16(acc[mi][ni], al, bh[ni]);
                }
            }
        }
    };

    // prologue: stage 0 filled; regs hold chunk 1
    ldgA(0); stsA(0); cpB(0, 0); CP_COMMIT();
    ldgA(1);

    #pragma unroll 1
    for (int c = 0; c < G1_NC; c++) {
        if (c + 1 < G1_NC) {
            int stg = (c + 1) & 1;
            stsA(stg);                    // regs from ldgA(c+1)
            cpB(c + 1, stg); CP_COMMIT();
            if (c + 2 < G1_NC) ldgA(c + 2);
        }
        if (c == G1_NC - 1) { CP_WAIT0(); } else { CP_WAIT1(); }
        __syncthreads();
        compute(c & 1);
        __syncthreads();                  // stage reuse fence (2-stage)
    }

    int mrow = lane >> 2, kcol = (lane & 3) * 2;
    #pragma unroll
    for (int mi = 0; mi < 4; mi++)
        #pragma unroll
        for (int ni = 0; ni < 4; ni++) {
            int kg = wn + ni * 8 + kcol;
            float c00 = g_c0[r * K_ + kg], c01 = g_c0[r * K_ + kg + 1];
            int m0 = n0 + wm + mi * 16 + mrow;
            #pragma unroll
            for (int half = 0; half < 2; half++) {
                float v0 = acc[mi][ni][half * 2 + 0] - c00;
                float v1 = acc[mi][ni][half * 2 + 1] - c01;
                __nv_bfloat16 h0, l0, h1, l1;
                split1(v0, h0, l0);
                split1(v1, h1, l1);
                size_t o = (size_t)(m0 + half * 8) * RK_ + r * K_ + kg;
                *(uint32_t*)(g_chi + o) = pack2(h0, h1);
                *(uint32_t*)(g_clo + o) = pack2(l0, l1);
            }
        }
}

// ---------------------------------------------------------------------------
// GEMM2 (mma.sync bf16x3): part[ks][n][d] = sum_j coeffs[n,j] * invbT[d,j]
// Block 256(n) x 128(d) x BK=32(j), split-K=6. grid=(4, 6, 6) = 144 CTAs.
// 512 thr, 16 warps 4x4, 64x32 per warp.
// ---------------------------------------------------------------------------
__global__ __launch_bounds__(512)
void gemm2_mma() {
    extern __shared__ __align__(128) char sm[];
    uint32_t sbase = smem_u32(sm);
    int tid = threadIdx.x, lane = tid & 31, wid = tid >> 5;
    int n0 = blockIdx.x * 256, d0 = blockIdx.y * 128, ks = blockIdx.z;
    int jbase = ks * (RK_ / KSPLIT);   // 2048 per split
    int wm = (wid >> 2) * 64, wn = (wid & 3) * 32;

    const __nv_bfloat16* Ah = g_chi  + (size_t)n0 * RK_ + jbase;
    const __nv_bfloat16* Al = g_clo  + (size_t)n0 * RK_ + jbase;
    const __nv_bfloat16* Bh = g_ibth + (size_t)d0 * RK_ + jbase;
    const __nv_bfloat16* Bl = g_ibtl + (size_t)d0 * RK_ + jbase;

    float acc[4][4][4];
    #pragma unroll
    for (int a = 0; a < 4; a++)
        #pragma unroll
        for (int b = 0; b < 4; b++)
            #pragma unroll
            for (int c = 0; c < 4; c++) acc[a][b][c] = 0.0f;

    int frow = tid >> 2, fch = tid & 3;   // frow 0..127

    auto fill = [&](int c, int stg) {
        uint32_t b = sbase + stg * STG2_BYTES;
        int j0 = c * 32;
        #pragma unroll
        for (int i = 0; i < 2; i++) {
            int rw = frow + 128 * i;
            uint32_t off = rw * 64 + ((fch ^ ((rw >> 1) & 3)) << 4);
            size_t so = (size_t)rw * RK_ + j0 + fch * 8;
            cp16(b +        off, Ah + so);
            cp16(b + A2_T + off, Al + so);
        }
        {
            int rw = frow;
            uint32_t off = rw * 64 + ((fch ^ ((rw >> 1) & 3)) << 4);
            size_t so = (size_t)rw * RK_ + j0 + fch * 8;
            cp16(b + 2 * A2_T +        off, Bh + so);
            cp16(b + 2 * A2_T + B2_T + off, Bl + so);
        }
    };

    auto compute = [&](int stg) {
        uint32_t b = sbase + stg * STG2_BYTES;
        #pragma unroll
        for (int kk = 0; kk < 2; kk++) {
            int lc = kk * 2 + (lane >> 4);
            uint32_t bh[4][2], bl[4][2];
            #pragma unroll
            for (int bi = 0; bi < 2; bi++) {
                int rw = wn + bi * 16 + (lane & 15);
                uint32_t off = rw * 64 + ((lc ^ ((rw >> 1) & 3)) << 4);
                uint32_t t[4];
                ldsm4(t, b + 2 * A2_T + off);
                bh[2*bi][0] = t[0]; bh[2*bi][1] = t[2];
                bh[2*bi+1][0] = t[1]; bh[2*bi+1][1] = t[3];
                ldsm4(t, b + 2 * A2_T + B2_T + off);
                bl[2*bi][0] = t[0]; bl[2*bi][1] = t[2];
                bl[2*bi+1][0] = t[1]; bl[2*bi+1][1] = t[3];
            }
            #pragma unroll
            for (int mi = 0; mi < 4; mi++) {
                int rw = wm + mi * 16 + (lane & 15);
                uint32_t off = rw * 64 + ((lc ^ ((rw >> 1) & 3)) << 4);
                uint32_t ah[4], al[4];
                ldsm4(ah, b + off);
                ldsm4(al, b + A2_T + off);
                #pragma unroll
                for (int ni = 0; ni < 4; ni++) {
                    mma_bf16(acc[mi][ni], ah, bh[ni]);
                    mma_bf16(acc[mi][ni], ah, bl[ni]);
                    mma_bf16(acc[mi][ni], al, bh[ni]);
                }
            }
        }
    };

    const int NC = (RK_ / KSPLIT) / 32;   // 64
    fill(0, 0); CP_COMMIT();
    fill(1, 1); CP_COMMIT();
    #pragma unroll 1
    for (int c = 0; c < NC; c++) {
        if (c == NC - 1) { CP_WAIT0(); } else { CP_WAIT1(); }
        __syncthreads();
        if (c + 2 < NC) { fill(c + 2, (c + 2) % NSTG2); CP_COMMIT(); }
        compute(c % NSTG2);
    }

    int mrow = lane >> 2, kcol = (lane & 3) * 2;
    #pragma unroll
    for (int mi = 0; mi < 4; mi++)
        #pragma unroll
        for (int ni = 0; ni < 4; ni++) {
            int dg = d0 + wn + ni * 8 + kcol;
            int m0 = n0 + wm + mi * 16 + mrow;
            #pragma unroll
            for (int half = 0; half < 2; half++) {
                float2 v = make_float2(acc[mi][ni][half * 2 + 0],
                                       acc[mi][ni][half * 2 + 1]);
                *(float2*)(g_part + ((size_t)ks * N_ + m0 + half * 8) * D_ + dg) = v;
            }
        }
}

// ---------------------------------------------------------------------------
// Final: out[n,d] = sum_a x[n,abl[a],d] + sum_ks part[ks][n][d]
// ---------------------------------------------------------------------------
__global__ void reduce_out(const float* __restrict__ x,
                           const int* __restrict__ abl,
                           float* __restrict__ out) {
    __shared__ int sabl[ABL_];
    if (threadIdx.x < ABL_) sabl[threadIdx.x] = abl[threadIdx.x];
    __syncthreads();

    size_t i4 = ((size_t)blockIdx.x * blockDim.x + threadIdx.x) * 4;
    int n = (int)(i4 / D_);
    int d = (int)(i4 - (size_t)n * D_);
    const float* xp = x + (size_t)n * S_ * D_ + d;

    float4 s = make_float4(0.f, 0.f, 0.f, 0.f);
    #pragma unroll
    for (int a = 0; a < ABL_; a++) {
        float4 v = __ldg((const float4*)(xp + (size_t)sabl[a] * D_));
        s.x += v.x; s.y += v.y; s.z += v.z; s.w += v.w;
    }
    #pragma unroll
    for (int ks = 0; ks < KSPLIT; ks++) {
        float4 p = *(const float4*)(g_part + (size_t)ks * N_ * D_ + i4);
        s.x += p.x; s.y += p.y; s.z += p.z; s.w += p.w;
    }
    *(float4*)(out + i4) = s;
}

// ---------------------------------------------------------------------------
// Launch
// ---------------------------------------------------------------------------
extern "C" void kernel_launch(void* const* d_in, const int* in_sizes, int n_in,
                              void* d_out, int out_size) {
    const float* x       = (const float*)d_in[0];
    const float* lambdas = (const float*)d_in[1];
    const float* bases   = (const float*)d_in[2];
    const float* invb    = (const float*)d_in[3];
    const float* means   = (const float*)d_in[4];
    const int*   resid   = (const int*)d_in[5];
    const int*   abl     = (const int*)d_in[6];
    const int*   lengths = (const int*)d_in[7];
    float*       out     = (float*)d_out;

    int total_lam = in_sizes[1];

    cudaFuncSetAttribute(gemm1_mma, cudaFuncAttributeMaxDynamicSharedMemorySize, SMEM_G1);
    cudaFuncSetAttribute(gemm2_mma, cudaFuncAttributeMaxDynamicSharedMemorySize, SMEM_G2);

    prep_blam<<<R_, 256>>>(lambdas, bases, means, lengths, total_lam);
    convert_ibt<<<dim3(RK_ / 32, D_ / 32), dim3(32, 8)>>>(invb);
    gemm1_mma<<<dim3(N_ / 128, R_), 256, SMEM_G1>>>(x, resid);
    gemm2_mma<<<dim3(N_ / 256, D_ / 128, KSPLIT), 512, SMEM_G2>>>();
    reduce_out<<<(N_ * D_ / 4) / 256, 256>>>(x, abl, out);
}

// round 11
// speedup vs baseline: 4.9859x; 1.0212x over previous
#include <cuda_runtime.h>
#include <cuda_bf16.h>
#include <cstdint>

#define N_   1024
#define S_   144
#define R_   96
#define K_   128
#define D_   768
#define ABL_ 48
#define RK_  (R_ * K_)   // 12288
#define KSPLIT 6

// ---------------------------------------------------------------------------
// Device-global scratch
// ---------------------------------------------------------------------------
__device__ float g_c0[RK_];
__device__ __align__(16) __nv_bfloat16 g_blh[(size_t)R_ * K_ * D_];
__device__ __align__(16) __nv_bfloat16 g_bll[(size_t)R_ * K_ * D_];
__device__ __align__(16) __nv_bfloat16 g_chi[(size_t)N_ * RK_];
__device__ __align__(16) __nv_bfloat16 g_clo[(size_t)N_ * RK_];
__device__ __align__(16) __nv_bfloat16 g_ibth[(size_t)D_ * RK_];
__device__ __align__(16) __nv_bfloat16 g_ibtl[(size_t)D_ * RK_];
__device__ float g_part[(size_t)KSPLIT * N_ * D_];

// ---------------------------------------------------------------------------
// Helpers
// ---------------------------------------------------------------------------
__device__ __forceinline__ uint32_t smem_u32(const void* p) {
    uint32_t a;
    asm("{ .reg .u64 t; cvta.to.shared.u64 t, %1; cvt.u32.u64 %0, t; }"
        : "=r"(a) : "l"(p));
    return a;
}

__device__ __forceinline__ void cp16(uint32_t dst, const void* src) {
    asm volatile("cp.async.cg.shared.global [%0], [%1], 16;" :: "r"(dst), "l"(src));
}
#define CP_COMMIT() asm volatile("cp.async.commit_group;" ::: "memory")
#define CP_WAIT0()  asm volatile("cp.async.wait_group 0;"  ::: "memory")

__device__ __forceinline__ void ldsm4(uint32_t* r, uint32_t a) {
    asm volatile("ldmatrix.sync.aligned.m8n8.x4.shared.b16 {%0,%1,%2,%3}, [%4];"
        : "=r"(r[0]), "=r"(r[1]), "=r"(r[2]), "=r"(r[3]) : "r"(a));
}

__device__ __forceinline__ void mma_bf16(float* d, const uint32_t* a, const uint32_t* b) {
    asm volatile(
        "mma.sync.aligned.m16n8k16.row.col.f32.bf16.bf16.f32 "
        "{%0,%1,%2,%3}, {%4,%5,%6,%7}, {%8,%9}, {%0,%1,%2,%3};"
        : "+f"(d[0]), "+f"(d[1]), "+f"(d[2]), "+f"(d[3])
        : "r"(a[0]), "r"(a[1]), "r"(a[2]), "r"(a[3]), "r"(b[0]), "r"(b[1]));
}

__device__ __forceinline__ void split1(float v, __nv_bfloat16& h, __nv_bfloat16& l) {
    h = __float2bfloat16(v);
    l = __float2bfloat16(v - __bfloat162float(h));
}
__device__ __forceinline__ uint32_t pack2(__nv_bfloat16 a, __nv_bfloat16 b) {
    uint16_t x = *(uint16_t*)&a, y = *(uint16_t*)&b;
    return (uint32_t)x | ((uint32_t)y << 16);
}

// GEMM1 smem: 64B rows (32 bf16), swizzle: phys chunk = ch ^ ((row>>1)&3)
#define TILE_BYTES 8192
#define STG_BYTES  32768   // Ah|Al|Bh|Bl @ 8KB
#define SMEM_G1 (2 * STG_BYTES)
#define SW1(rw, ch4) ((rw) * 64 + (((ch4) ^ (((rw) >> 1) & 3)) << 4))

// GEMM2 smem: 128B rows (64 bf16), swizzle: phys chunk = ch ^ (row&7)
#define A2T 32768          // 256 x 64 bf16
#define B2T 16384          // 128 x 64 bf16
#define STG2_BYTES (2 * A2T + 2 * B2T)   // 98304
#define SMEM_G2 (2 * STG2_BYTES)         // 196608
#define SW2(rw, ch8) ((rw) * 128 + (((ch8) ^ ((rw) & 7)) << 4))

// ---------------------------------------------------------------------------
// prep + blam convert fused
// ---------------------------------------------------------------------------
__global__ void prep_blam(const float* __restrict__ lambdas,
                          const float* __restrict__ bases,
                          const float* __restrict__ means,
                          const int*   __restrict__ lengths,
                          int total_lam) {
    int r = blockIdx.x, tid = threadIdx.x;

    __shared__ float smean[D_];
    __shared__ float slam[K_];
    __shared__ float sdot[256];

    for (int d = tid; d < D_; d += 256)
        smean[d] = means[r * D_ + d];
    __syncthreads();

    int off = 0;
    for (int i = 0; i < r; i++) off += lengths[i];
    int len = lengths[r];

    int k = tid >> 1, h = tid & 1;
    const float* brow = bases + ((size_t)r * K_ + k) * D_;
    float dot = 0.0f;
    #pragma unroll 8
    for (int d = h * (D_ / 2); d < (h + 1) * (D_ / 2); d++)
        dot += smean[d] * brow[d];
    sdot[tid] = dot;
    __syncthreads();

    if (h == 0) {
        float lam = 0.0f;
        if (k < len) {
            int idx = off + k;
            if (idx > total_lam - 1) idx = total_lam - 1;
            lam = lambdas[idx];
        }
        g_c0[r * K_ + k] = lam * (sdot[tid] + sdot[tid + 1]);
        slam[k] = lam;
    }
    __syncthreads();

    const float* bbase = bases + (size_t)r * K_ * D_;
    for (int i4 = tid * 4; i4 < K_ * D_; i4 += 256 * 4) {
        float lam = slam[i4 / D_];
        float4 v = *(const float4*)(bbase + i4);
        __align__(8) __nv_bfloat16 hh[4], ll[4];
        split1(v.x * lam, hh[0], ll[0]); split1(v.y * lam, hh[1], ll[1]);
        split1(v.z * lam, hh[2], ll[2]); split1(v.w * lam, hh[3], ll[3]);
        size_t o = (size_t)r * K_ * D_ + i4;
        *(uint2*)(g_blh + o) = *(uint2*)hh;
        *(uint2*)(g_bll + o) = *(uint2*)ll;
    }
}

// invb [j][d] -> transposed bf16 hi/lo [d][j]
__global__ void convert_ibt(const float* __restrict__ invb) {
    __shared__ float t[32][33];
    int jb = blockIdx.x * 32, db = blockIdx.y * 32;
    int tx = threadIdx.x, ty = threadIdx.y;  // 32 x 8
    #pragma unroll
    for (int k = 0; k < 4; k++)
        t[ty + 8 * k][tx] = invb[(size_t)(jb + ty + 8 * k) * D_ + db + tx];
    __syncthreads();
    #pragma unroll
    for (int k = 0; k < 4; k++) {
        float v = t[tx][ty + 8 * k];
        __nv_bfloat16 h, l;
        split1(v, h, l);
        size_t o = (size_t)(db + ty + 8 * k) * RK_ + jb + tx;
        g_ibth[o] = h;
        g_ibtl[o] = l;
    }
}

// ablated-slice sum -> out (3rd launch so gemm1 is the profiled 4th)
__global__ void abl_kernel(const float* __restrict__ x,
                           const int* __restrict__ abl,
                           float* __restrict__ out) {
    __shared__ int sabl[ABL_];
    if (threadIdx.x < ABL_) sabl[threadIdx.x] = abl[threadIdx.x];
    __syncthreads();

    size_t i4 = ((size_t)blockIdx.x * blockDim.x + threadIdx.x) * 4;
    int n = (int)(i4 / D_);
    int d = (int)(i4 - (size_t)n * D_);
    const float* xp = x + (size_t)n * S_ * D_ + d;

    float4 s = make_float4(0.f, 0.f, 0.f, 0.f);
    #pragma unroll
    for (int a = 0; a < ABL_; a++) {
        float4 v = __ldg((const float4*)(xp + (size_t)sabl[a] * D_));
        s.x += v.x; s.y += v.y; s.z += v.z; s.w += v.w;
    }
    *(float4*)(out + i4) = s;
}

// ---------------------------------------------------------------------------
// GEMM1 (mma.sync bf16x3, fused gather+split, 2-stage, ONE sync per chunk)
// Block 128(m) x 128(k) x BK=32. grid=(8, 96), 256 thr, 2 CTAs/SM.
// ---------------------------------------------------------------------------
#define G1_NC 24

__global__ __launch_bounds__(256, 2)
void gemm1_mma(const float* __restrict__ x, const int* __restrict__ resid) {
    extern __shared__ __align__(128) char sm[];
    uint32_t sbase = smem_u32(sm);
    int tid = threadIdx.x, lane = tid & 31, wid = tid >> 5;
    int r = blockIdx.y, n0 = blockIdx.x * 128;
    int s = __ldg(resid + r);
    int wm = (wid >> 2) * 64, wn = (wid & 3) * 32;

    const float* Ax = x + ((size_t)n0 * S_ + s) * D_;
    const __nv_bfloat16* Bh = g_blh + (size_t)r * K_ * D_;
    const __nv_bfloat16* Bl = g_bll + (size_t)r * K_ * D_;

    float acc[4][4][4];
    #pragma unroll
    for (int a = 0; a < 4; a++)
        #pragma unroll
        for (int b = 0; b < 4; b++)
            #pragma unroll
            for (int c = 0; c < 4; c++) acc[a][b][c] = 0.0f;

    int frow = tid >> 2, fch = tid & 3;
    float4 ra[4];

    auto ldgA = [&](int c) {
        int d0 = c * 32;
        #pragma unroll
        for (int i = 0; i < 2; i++) {
            int rw = frow + 64 * i;
            const float* p = Ax + (size_t)rw * (S_ * D_) + d0 + fch * 8;
            ra[2 * i]     = __ldg((const float4*)p);
            ra[2 * i + 1] = __ldg((const float4*)(p + 4));
        }
    };

    auto stsA = [&](int stg) {
        char* b = sm + stg * STG_BYTES;
        #pragma unroll
        for (int i = 0; i < 2; i++) {
            int rw = frow + 64 * i;
            uint32_t off = SW1(rw, fch);
            float vv[8] = {ra[2*i].x, ra[2*i].y, ra[2*i].z, ra[2*i].w,
                           ra[2*i+1].x, ra[2*i+1].y, ra[2*i+1].z, ra[2*i+1].w};
            __align__(16) __nv_bfloat16 h[8], l[8];
            #pragma unroll
            for (int j = 0; j < 8; j++) split1(vv[j], h[j], l[j]);
            *(uint4*)(b + off)              = *(uint4*)h;
            *(uint4*)(b + TILE_BYTES + off) = *(uint4*)l;
        }
    };

    auto cpB = [&](int c, int stg) {
        uint32_t b = sbase + stg * STG_BYTES;
        int d0 = c * 32;
        #pragma unroll
        for (int i = 0; i < 2; i++) {
            int rw = frow + 64 * i;
            uint32_t off = SW1(rw, fch);
            size_t so = (size_t)rw * D_ + d0 + fch * 8;
            cp16(b + 2 * TILE_BYTES + off, Bh + so);
            cp16(b + 3 * TILE_BYTES + off, Bl + so);
        }
    };

    auto compute = [&](int stg) {
        uint32_t b = sbase + stg * STG_BYTES;
        #pragma unroll
        for (int kk = 0; kk < 2; kk++) {
            int lc = kk * 2 + (lane >> 4);
            uint32_t bh[4][2], bl[4][2];
            #pragma unroll
            for (int bi = 0; bi < 2; bi++) {
                int rw = wn + bi * 16 + (lane & 15);
                uint32_t off = SW1(rw, lc);
                uint32_t t[4];
                ldsm4(t, b + 2 * TILE_BYTES + off);
                bh[2*bi][0] = t[0]; bh[2*bi][1] = t[2];
                bh[2*bi+1][0] = t[1]; bh[2*bi+1][1] = t[3];
                ldsm4(t, b + 3 * TILE_BYTES + off);
                bl[2*bi][0] = t[0]; bl[2*bi][1] = t[2];
                bl[2*bi+1][0] = t[1]; bl[2*bi+1][1] = t[3];
            }
            #pragma unroll
            for (int mi = 0; mi < 4; mi++) {
                int rw = wm + mi * 16 + (lane & 15);
                uint32_t off = SW1(rw, lc);
                uint32_t ah[4], al[4];
                ldsm4(ah, b + off);
                ldsm4(al, b + TILE_BYTES + off);
                #pragma unroll
                for (int ni = 0; ni < 4; ni++) {
                    mma_bf16(acc[mi][ni], ah, bh[ni]);
                    mma_bf16(acc[mi][ni], ah, bl[ni]);
                    mma_bf16(acc[mi][ni], al, bh[ni]);
                }
            }
        }
    };

    // prologue: stage 0 filled; regs hold chunk 1
    ldgA(0); stsA(0); cpB(0, 0); CP_COMMIT();
    ldgA(1);

    #pragma unroll 1
    for (int c = 0; c < G1_NC; c++) {
        CP_WAIT0();
        __syncthreads();     // orders compute(c-1) before refilling its stage
        if (c + 1 < G1_NC) {
            int stg = (c + 1) & 1;
            stsA(stg);
            cpB(c + 1, stg); CP_COMMIT();
            if (c + 2 < G1_NC) ldgA(c + 2);
        }
        compute(c & 1);
    }

    int mrow = lane >> 2, kcol = (lane & 3) * 2;
    #pragma unroll
    for (int mi = 0; mi < 4; mi++)
        #pragma unroll
        for (int ni = 0; ni < 4; ni++) {
            int kg = wn + ni * 8 + kcol;
            float c00 = g_c0[r * K_ + kg], c01 = g_c0[r * K_ + kg + 1];
            int m0 = n0 + wm + mi * 16 + mrow;
            #pragma unroll
            for (int half = 0; half < 2; half++) {
                float v0 = acc[mi][ni][half * 2 + 0] - c00;
                float v1 = acc[mi][ni][half * 2 + 1] - c01;
                __nv_bfloat16 h0, l0, h1, l1;
                split1(v0, h0, l0);
                split1(v1, h1, l1);
                size_t o = (size_t)(m0 + half * 8) * RK_ + r * K_ + kg;
                *(uint32_t*)(g_chi + o) = pack2(h0, h1);
                *(uint32_t*)(g_clo + o) = pack2(l0, l1);
            }
        }
}

// ---------------------------------------------------------------------------
// GEMM2 (mma.sync bf16x3): BK=64, 2-stage, ONE sync per chunk.
// Block 256(n) x 128(d), split-K=6 (2048 j, 32 chunks). grid=(4,6,6)=144 CTAs.
// 512 thr, 16 warps 4x4, 64x32 per warp. smem 96KB/stage x2.
// ---------------------------------------------------------------------------
__global__ __launch_bounds__(512)
void gemm2_mma() {
    extern __shared__ __align__(128) char sm[];
    uint32_t sbase = smem_u32(sm);
    int tid = threadIdx.x, lane = tid & 31, wid = tid >> 5;
    int n0 = blockIdx.x * 256, d0 = blockIdx.y * 128, ks = blockIdx.z;
    int jbase = ks * (RK_ / KSPLIT);
    int wm = (wid >> 2) * 64, wn = (wid & 3) * 32;

    const __nv_bfloat16* Ah = g_chi  + (size_t)n0 * RK_ + jbase;
    const __nv_bfloat16* Al = g_clo  + (size_t)n0 * RK_ + jbase;
    const __nv_bfloat16* Bh = g_ibth + (size_t)d0 * RK_ + jbase;
    const __nv_bfloat16* Bl = g_ibtl + (size_t)d0 * RK_ + jbase;

    float acc[4][4][4];
    #pragma unroll
    for (int a = 0; a < 4; a++)
        #pragma unroll
        for (int b = 0; b < 4; b++)
            #pragma unroll
            for (int c = 0; c < 4; c++) acc[a][b][c] = 0.0f;

    int rw0 = tid >> 3, fch = tid & 7;   // 64 rows per pass, 8 chunks of 16B per 128B row

    auto fill = [&](int c, int stg) {
        uint32_t b = sbase + stg * STG2_BYTES;
        int j0 = c * 64;
        #pragma unroll
        for (int i = 0; i < 4; i++) {
            int rw = rw0 + 64 * i;
            uint32_t off = SW2(rw, fch);
            size_t so = (size_t)rw * RK_ + j0 + fch * 8;
            cp16(b +       off, Ah + so);
            cp16(b + A2T + off, Al + so);
        }
        #pragma unroll
        for (int i = 0; i < 2; i++) {
            int rw = rw0 + 64 * i;
            uint32_t off = SW2(rw, fch);
            size_t so = (size_t)rw * RK_ + j0 + fch * 8;
            cp16(b + 2 * A2T +       off, Bh + so);
            cp16(b + 2 * A2T + B2T + off, Bl + so);
        }
    };

    auto compute = [&](int stg) {
        uint32_t b = sbase + stg * STG2_BYTES;
        #pragma unroll
        for (int kk = 0; kk < 4; kk++) {
            int lc = kk * 2 + (lane >> 4);
            uint32_t bh[4][2], bl[4][2];
            #pragma unroll
            for (int bi = 0; bi < 2; bi++) {
                int rw = wn + bi * 16 + (lane & 15);
                uint32_t off = SW2(rw, lc);
                uint32_t t[4];
                ldsm4(t, b + 2 * A2T + off);
                bh[2*bi][0] = t[0]; bh[2*bi][1] = t[2];
                bh[2*bi+1][0] = t[1]; bh[2*bi+1][1] = t[3];
                ldsm4(t, b + 2 * A2T + B2T + off);
                bl[2*bi][0] = t[0]; bl[2*bi][1] = t[2];
                bl[2*bi+1][0] = t[1]; bl[2*bi+1][1] = t[3];
            }
            #pragma unroll
            for (int mi = 0; mi < 4; mi++) {
                int rw = wm + mi * 16 + (lane & 15);
                uint32_t off = SW2(rw, lc);
                uint32_t ah[4], al[4];
                ldsm4(ah, b + off);
                ldsm4(al, b + A2T + off);
                #pragma unroll
                for (int ni = 0; ni < 4; ni++) {
                    mma_bf16(acc[mi][ni], ah, bh[ni]);
                    mma_bf16(acc[mi][ni], ah, bl[ni]);
                    mma_bf16(acc[mi][ni], al, bh[ni]);
                }
            }
        }
    };

    const int NC = (RK_ / KSPLIT) / 64;   // 32
    fill(0, 0); CP_COMMIT();
    #pragma unroll 1
    for (int c = 0; c < NC; c++) {
        CP_WAIT0();
        __syncthreads();
        if (c + 1 < NC) { fill(c + 1, (c + 1) & 1); CP_COMMIT(); }
        compute(c & 1);
    }

    int mrow = lane >> 2, kcol = (lane & 3) * 2;
    #pragma unroll
    for (int mi = 0; mi < 4; mi++)
        #pragma unroll
        for (int ni = 0; ni < 4; ni++) {
            int dg = d0 + wn + ni * 8 + kcol;
            int m0 = n0 + wm + mi * 16 + mrow;
            #pragma unroll
            for (int half = 0; half < 2; half++) {
                float2 v = make_float2(acc[mi][ni][half * 2 + 0],
                                       acc[mi][ni][half * 2 + 1]);
                *(float2*)(g_part + ((size_t)ks * N_ + m0 + half * 8) * D_ + dg) = v;
            }
        }
}

// out += sum of KSPLIT partials (out already holds ablated sum)
__global__ void reduce_out(float* __restrict__ out) {
    size_t i4 = ((size_t)blockIdx.x * blockDim.x + threadIdx.x) * 4;
    float4 o = *(float4*)(out + i4);
    #pragma unroll
    for (int ks = 0; ks < KSPLIT; ks++) {
        float4 p = *(const float4*)(g_part + (size_t)ks * N_ * D_ + i4);
        o.x += p.x; o.y += p.y; o.z += p.z; o.w += p.w;
    }
    *(float4*)(out + i4) = o;
}

// ---------------------------------------------------------------------------
// Launch (order matters: gemm1 is the 4th launch -> profiled next round)
// ---------------------------------------------------------------------------
extern "C" void kernel_launch(void* const* d_in, const int* in_sizes, int n_in,
                              void* d_out, int out_size) {
    const float* x       = (const float*)d_in[0];
    const float* lambdas = (const float*)d_in[1];
    const float* bases   = (const float*)d_in[2];
    const float* invb    = (const float*)d_in[3];
    const float* means   = (const float*)d_in[4];
    const int*   resid   = (const int*)d_in[5];
    const int*   abl     = (const int*)d_in[6];
    const int*   lengths = (const int*)d_in[7];
    float*       out     = (float*)d_out;

    int total_lam = in_sizes[1];

    cudaFuncSetAttribute(gemm1_mma, cudaFuncAttributeMaxDynamicSharedMemorySize, SMEM_G1);
    cudaFuncSetAttribute(gemm2_mma, cudaFuncAttributeMaxDynamicSharedMemorySize, SMEM_G2);

    prep_blam<<<R_, 256>>>(lambdas, bases, means, lengths, total_lam);
    convert_ibt<<<dim3(RK_ / 32, D_ / 32), dim3(32, 8)>>>(invb);
    abl_kernel<<<(N_ * D_ / 4) / 256, 256>>>(x, abl, out);
    gemm1_mma<<<dim3(N_ / 128, R_), 256, SMEM_G1>>>(x, resid);
    gemm2_mma<<<dim3(N_ / 256, D_ / 128, KSPLIT), 512, SMEM_G2>>>();
    reduce_out<<<(N_ * D_ / 4) / 256, 256>>>(out);
}